// round 14
// baseline (speedup 1.0000x reference)
#include <cuda_runtime.h>
#include <cuda_bf16.h>
#include <math.h>
#include <stdint.h>

// Problem constants
#define Bb 16
#define Ee 512
#define Tt 512
#define Hh 1024
#define Rr 32
#define Pp 8192
#define Ww 3
#define KSPLIT 4

// bf16 m16n8k16 tensor-core MMA (baseline PTX, valid on sm_103)
#define MMA16816(C, A, B) \
    asm volatile("mma.sync.aligned.m16n8k16.row.col.f32.bf16.bf16.f32 " \
        "{%0,%1,%2,%3}, {%4,%5,%6,%7}, {%8,%9}, {%0,%1,%2,%3};" \
        : "+f"((C)[0]), "+f"((C)[1]), "+f"((C)[2]), "+f"((C)[3]) \
        : "r"((A)[0]), "r"((A)[1]), "r"((A)[2]), "r"((A)[3]), \
          "r"((B)[0]), "r"((B)[1]))

#define LDSM_X4(R0, R1, R2, R3, addr) \
    asm volatile("ldmatrix.sync.aligned.m8n8.x4.shared.b16 {%0,%1,%2,%3}, [%4];" \
        : "=r"(R0), "=r"(R1), "=r"(R2), "=r"(R3) : "r"(addr))

__device__ __forceinline__ uint32_t smem_u32(const void* p) {
    uint32_t a;
    asm("{ .reg .u64 t; cvta.to.shared.u64 t, %1; cvt.u32.u64 %0, t; }" : "=r"(a) : "l"(p));
    return a;
}

// Scratch (device globals: allocation-free per harness rules)
__device__ float g_x1[Bb*Ee*Tt];                 // conv1 out fp32 (B,E,T)
__device__ float g_xbte[Bb*Tt*Ee];               // conv2 out fp32 (B,T,E)
__device__ __nv_bfloat16 g_xh[Bb*Tt*Ee];         // input x hi/lo (B,T,E) !
__device__ __nv_bfloat16 g_xl[Bb*Tt*Ee];
__device__ __nv_bfloat16 g_x1h[Bb*Tt*Ee];        // conv1 out hi/lo (B,T,E) !
__device__ __nv_bfloat16 g_x1l[Bb*Tt*Ee];
__device__ __nv_bfloat16 g_wt1h[3*Ee*Ee];        // conv weights [dk][eo][ei]
__device__ __nv_bfloat16 g_wt1l[3*Ee*Ee];
__device__ __nv_bfloat16 g_wt2h[3*Ee*Ee];
__device__ __nv_bfloat16 g_wt2l[3*Ee*Ee];
__device__ __nv_bfloat16 g_mx_h[Pp*Ee];
__device__ __nv_bfloat16 g_mx_l[Pp*Ee];
__device__ __nv_bfloat16 g_w1h[Hh*Ee];
__device__ __nv_bfloat16 g_w1l[Hh*Ee];
__device__ __nv_bfloat16 g_w2h[Hh*Hh];
__device__ __nv_bfloat16 g_w2l[Hh*Hh];
__device__ __nv_bfloat16 g_h1h[Pp*Hh];
__device__ __nv_bfloat16 g_h1l[Pp*Hh];
__device__ float g_h2[Pp*Hh];
__device__ float g_fc3p[KSPLIT*Pp*Rr];

// fp32 -> bf16 hi/lo (elementwise, for FC weights)
__global__ void cvt_hilo_kernel(const float* __restrict__ in,
                                __nv_bfloat16* __restrict__ hi,
                                __nv_bfloat16* __restrict__ lo, int n)
{
    int i = blockIdx.x * blockDim.x + threadIdx.x;
    if (i < n) {
        float x = in[i];
        __nv_bfloat16 h = __float2bfloat16(x);
        hi[i] = h;
        lo[i] = __float2bfloat16(x - __bfloat162float(h));
    }
}

// fp32 (B,E,T) -> bf16 hi/lo (B,T,E), 32x32 smem transpose
__global__ __launch_bounds__(256) void cvt_transpose_kernel(
    const float* __restrict__ in,
    __nv_bfloat16* __restrict__ hi,
    __nv_bfloat16* __restrict__ lo)
{
    __shared__ float tile[32][33];
    const int b  = blockIdx.z;
    const int e0 = blockIdx.y * 32;
    const int t0 = blockIdx.x * 32;
    const int tx = threadIdx.x & 31;
    const int ty = threadIdx.x >> 5;    // 0..7

    #pragma unroll
    for (int r = ty; r < 32; r += 8)
        tile[r][tx] = in[((size_t)b * Ee + e0 + r) * Tt + t0 + tx];
    __syncthreads();
    #pragma unroll
    for (int r = ty; r < 32; r += 8) {
        float v = tile[tx][r];          // (e_local=tx, t_local=r)
        __nv_bfloat16 h = __float2bfloat16(v);
        size_t o = ((size_t)b * Tt + t0 + r) * Ee + e0 + tx;
        hi[o] = h;
        lo[o] = __float2bfloat16(v - __bfloat162float(h));
    }
}

// conv weights (eo,ei,dk) -> transposed [dk][eo][ei] hi/lo
__global__ void cvt_wt_kernel(const float* __restrict__ w,
                              __nv_bfloat16* __restrict__ th,
                              __nv_bfloat16* __restrict__ tl)
{
    int i = blockIdx.x * blockDim.x + threadIdx.x;
    if (i < Ee * Ee * 3) {
        int eo  = i / (Ee * 3);
        int rem = i - eo * (Ee * 3);
        int ei  = rem / 3;
        int dk  = rem - ei * 3;
        float x = w[i];
        __nv_bfloat16 h = __float2bfloat16(x);
        int o = dk * (Ee * Ee) + eo * Ee + ei;
        th[o] = h;
        tl[o] = __float2bfloat16(x - __bfloat162float(h));
    }
}

// ---------------------------------------------------------------------------
// Conv residual block via mma.sync bf16x3 + ldmatrix; B via cp.async from
// (B,T,E)-layout hi/lo (fully async loads). Double-buffered.
// MODE 0: write g_x1 fp32 (B,E,T) + g_x1h/l bf16 (B,T,E)
// MODE 1: write g_xbte fp32 (B,T,E)
// ---------------------------------------------------------------------------
#define CROWB 80
#define CAH 0
#define CAL (384*CROWB)
#define CBH (2*384*CROWB)
#define CBL (CBH + 130*CROWB)
#define CBUF (CBL + 130*CROWB)
#define CONV_SMEM (2*CBUF)

template<int MODE>
__global__ __launch_bounds__(256, 1) void conv_mma_kernel(
    const __nv_bfloat16* __restrict__ xh_g, const __nv_bfloat16* __restrict__ xl_g,
    const __nv_bfloat16* __restrict__ wth,  const __nv_bfloat16* __restrict__ wtl,
    const float* __restrict__ bias, const float* __restrict__ resid,
    float* __restrict__ outf,
    __nv_bfloat16* __restrict__ outh, __nv_bfloat16* __restrict__ outl)
{
    extern __shared__ __align__(16) unsigned char SM[];

    const int tid  = threadIdx.x;
    const int wid  = tid >> 5;
    const int lane = tid & 31;
    const int g    = lane >> 2;
    const int tq   = lane & 3;
    const int n0   = blockIdx.x * 128;
    const int m0   = blockIdx.y * 128;
    const int b    = n0 >> 9;
    const int t0   = n0 & 511;
    const int wm   = wid & 1;
    const int wn   = wid >> 1;
    const uint32_t smbase = smem_u32(SM);

    const int lrow = lane & 15;
    const int lkh  = lane >> 4;
    const int brow = lane & 7;
    const int bkh  = (lane >> 3) & 1;
    const int bts  = lane >> 4;

    // (B,T,E) layout
    const __nv_bfloat16* __restrict__ xh_b = xh_g + (size_t)b * Tt * Ee;
    const __nv_bfloat16* __restrict__ xl_b = xl_g + (size_t)b * Tt * Ee;

    float acc[4][4][4];
    #pragma unroll
    for (int i = 0; i < 4; i++)
        #pragma unroll
        for (int j = 0; j < 4; j++)
            #pragma unroll
            for (int q = 0; q < 4; q++) acc[i][j][q] = 0.f;

    // ---- chunk loader: all cp.async ----
    auto issue = [&](int kbeg, int bsel) {
        uint32_t base = smbase + bsel * CBUF;
        unsigned char* bb = SM + bsel * CBUF;
        // A: weights, 3 taps x 128 eo x 32 ei, hi+lo = 3072 x 16B, 12/thread
        #pragma unroll
        for (int i = 0; i < 12; i++) {
            int idx = tid + 256 * i;
            int hl  = (idx >= 1536);
            int r   = hl ? (idx - 1536) : idx;
            int row = r >> 2;
            int q   = r & 3;
            int dk  = row >> 7;
            int eo  = row & 127;
            const __nv_bfloat16* gsrc =
                (hl ? wtl : wth) + (size_t)dk * (Ee * Ee) + (size_t)(m0 + eo) * Ee + kbeg + q * 8;
            uint32_t daddr = base + (hl ? CAL : CAH) + row * CROWB + q * 16;
            asm volatile("cp.async.cg.shared.global [%0], [%1], 16;"
                         :: "r"(daddr), "l"(gsrc));
        }
        // B: x (B,T,E): 130 rows (t0-1..t0+128) x 32 ei (64B = 4x16B), hi+lo
        // 1040 units, 5 iters with guard
        #pragma unroll
        for (int i = 0; i < 5; i++) {
            int idx = tid + 256 * i;
            if (idx < 1040) {
                int hl  = (idx >= 520);
                int r   = hl ? (idx - 520) : idx;
                int row = r >> 2;          // 0..129, global t = t0-1+row
                int u   = r & 3;
                int t   = t0 - 1 + row;
                uint32_t off = (hl ? CBL : CBH) + row * CROWB + u * 16;
                if ((unsigned)t < (unsigned)Tt) {
                    const __nv_bfloat16* gsrc =
                        (hl ? xl_b : xh_b) + (size_t)t * Ee + kbeg + u * 8;
                    asm volatile("cp.async.cg.shared.global [%0], [%1], 16;"
                                 :: "r"(base + off), "l"(gsrc));
                } else {
                    *(uint4*)(bb + off) = make_uint4(0, 0, 0, 0);
                }
            }
        }
        asm volatile("cp.async.commit_group;" ::: "memory");
    };

    // ---- compute one K=32 chunk (ldmatrix) ----
    auto compute = [&](int bsel) {
        const uint32_t base = smbase + bsel * CBUF;
        #pragma unroll
        for (int ko = 0; ko < 32; ko += 16) {
            #pragma unroll
            for (int dk = 0; dk < 3; dk++) {
                uint32_t ah[4][4], al[4][4], bh[4][2], bl[4][2];
                #pragma unroll
                for (int mt = 0; mt < 4; mt++) {
                    int row = dk * 128 + wm * 64 + mt * 16 + lrow;
                    uint32_t aoff = row * CROWB + (ko + 8 * lkh) * 2;
                    LDSM_X4(ah[mt][0], ah[mt][1], ah[mt][2], ah[mt][3], base + CAH + aoff);
                    LDSM_X4(al[mt][0], al[mt][1], al[mt][2], al[mt][3], base + CAL + aoff);
                }
                #pragma unroll
                for (int p = 0; p < 2; p++) {
                    int row = wn * 32 + p * 16 + bts * 8 + brow + dk;
                    uint32_t boff = row * CROWB + (ko + 8 * bkh) * 2;
                    LDSM_X4(bh[2*p][0], bh[2*p][1], bh[2*p+1][0], bh[2*p+1][1], base + CBH + boff);
                    LDSM_X4(bl[2*p][0], bl[2*p][1], bl[2*p+1][0], bl[2*p+1][1], base + CBL + boff);
                }
                #pragma unroll
                for (int mt = 0; mt < 4; mt++)
                    #pragma unroll
                    for (int nt = 0; nt < 4; nt++)
                        MMA16816(acc[mt][nt], ah[mt], bh[nt]);
                #pragma unroll
                for (int mt = 0; mt < 4; mt++)
                    #pragma unroll
                    for (int nt = 0; nt < 4; nt++)
                        MMA16816(acc[mt][nt], ah[mt], bl[nt]);
                #pragma unroll
                for (int mt = 0; mt < 4; mt++)
                    #pragma unroll
                    for (int nt = 0; nt < 4; nt++)
                        MMA16816(acc[mt][nt], al[mt], bh[nt]);
            }
        }
    };

    const int NC = Ee / 32;
    issue(0, 0);
    for (int c = 0; c < NC; c++) {
        if (c + 1 < NC) {
            issue((c + 1) * 32, (c + 1) & 1);
            asm volatile("cp.async.wait_group 1;" ::: "memory");
        } else {
            asm volatile("cp.async.wait_group 0;" ::: "memory");
        }
        __syncthreads();
        compute(c & 1);
        __syncthreads();
    }

    // ---- epilogue ----
    #pragma unroll
    for (int mt = 0; mt < 4; mt++) {
        const int eo0 = m0 + wm * 64 + mt * 16 + g;
        const int eo1 = eo0 + 8;
        const float b0v = bias[eo0], b1v = bias[eo1];
        #pragma unroll
        for (int nt = 0; nt < 4; nt++) {
            const int n = t0 + wn * 32 + nt * 8 + tq * 2;
            float v00 = acc[mt][nt][0] + b0v;
            float v01 = acc[mt][nt][1] + b0v;
            float v10 = acc[mt][nt][2] + b1v;
            float v11 = acc[mt][nt][3] + b1v;
            v00 = (v00 > 0.f) ? v00 : 0.f;
            v01 = (v01 > 0.f) ? v01 : 0.f;
            v10 = (v10 > 0.f) ? v10 : 0.f;
            v11 = (v11 > 0.f) ? v11 : 0.f;
            size_t i00 = ((size_t)b * Ee + eo0) * Tt + n;
            size_t i10 = ((size_t)b * Ee + eo1) * Tt + n;
            v00 += resid[i00];     v01 += resid[i00 + 1];
            v10 += resid[i10];     v11 += resid[i10 + 1];
            if (MODE == 0) {
                outf[i00] = v00; outf[i00 + 1] = v01;
                outf[i10] = v10; outf[i10 + 1] = v11;
                // hi/lo to (B,T,E) for conv2's async B loads
                size_t j00 = ((size_t)b * Tt + n) * Ee + eo0;  // (t=n, eo0)
                __nv_bfloat16 h00 = __float2bfloat16(v00);
                __nv_bfloat16 h01 = __float2bfloat16(v01);
                __nv_bfloat16 h10 = __float2bfloat16(v10);
                __nv_bfloat16 h11 = __float2bfloat16(v11);
                outh[j00]          = h00;
                outh[j00 + Ee]     = h01;
                outh[j00 + 8]      = h10;
                outh[j00 + Ee + 8] = h11;
                outl[j00]          = __float2bfloat16(v00 - __bfloat162float(h00));
                outl[j00 + Ee]     = __float2bfloat16(v01 - __bfloat162float(h01));
                outl[j00 + 8]      = __float2bfloat16(v10 - __bfloat162float(h10));
                outl[j00 + Ee + 8] = __float2bfloat16(v11 - __bfloat162float(h11));
            } else {
                outf[((size_t)b * Tt + n)     * Ee + eo0] = v00;
                outf[((size_t)b * Tt + n + 1) * Ee + eo0] = v01;
                outf[((size_t)b * Tt + n)     * Ee + eo1] = v10;
                outf[((size_t)b * Tt + n + 1) * Ee + eo1] = v11;
            }
        }
    }
}

// ---------------------------------------------------------------------------
// Span max gather -> bf16 hi/lo
// ---------------------------------------------------------------------------
__global__ __launch_bounds__(128) void span_kernel(
    const int* __restrict__ bidx,
    const int* __restrict__ hidx, const int* __restrict__ hspan,
    const int* __restrict__ tidx, const int* __restrict__ tspan)
{
    const int p  = blockIdx.x;
    const int e4 = threadIdx.x;
    const int b  = bidx[p];
    const float4* __restrict__ base = (const float4*)g_xbte + (size_t)b * Tt * (Ee / 4);

    const int h0 = hidx[p], hs = hspan[p];
    const int t0 = tidx[p], ts = tspan[p];

    float4 hm = make_float4(-INFINITY, -INFINITY, -INFINITY, -INFINITY);
    for (int s = 0; s < hs; s++) {
        float4 v = base[(size_t)(h0 + s) * (Ee / 4) + e4];
        hm.x = fmaxf(hm.x, v.x); hm.y = fmaxf(hm.y, v.y);
        hm.z = fmaxf(hm.z, v.z); hm.w = fmaxf(hm.w, v.w);
    }
    float4 tm = make_float4(-INFINITY, -INFINITY, -INFINITY, -INFINITY);
    for (int s = 0; s < ts; s++) {
        float4 v = base[(size_t)(t0 + s) * (Ee / 4) + e4];
        tm.x = fmaxf(tm.x, v.x); tm.y = fmaxf(tm.y, v.y);
        tm.z = fmaxf(tm.z, v.z); tm.w = fmaxf(tm.w, v.w);
    }
    float o[4] = {hm.x + tm.x, hm.y + tm.y, hm.z + tm.z, hm.w + tm.w};

    size_t off = (size_t)p * Ee + e4 * 4;
    #pragma unroll
    for (int j = 0; j < 4; j++) {
        __nv_bfloat16 h = __float2bfloat16(o[j]);
        __nv_bfloat16 l = __float2bfloat16(o[j] - __bfloat162float(h));
        g_mx_h[off + j] = h;
        g_mx_l[off + j] = l;
    }
}

// ---------------------------------------------------------------------------
// Tensor-core bf16x3 NT GEMM (FC1/FC2): ldmatrix + 3-stage cp.async ring,
// single __syncthreads per chunk.
// ---------------------------------------------------------------------------
#define SROW 40
#define SEC_ELEMS (128*SROW)
#define SEC_BYTES (SEC_ELEMS*2)
#define BUF_BYTES (4*SEC_BYTES)
#define FC_SMEM   (3*BUF_BYTES)

template<bool HILO>
__global__ __launch_bounds__(256, 1) void fc_mma_kernel(
    const __nv_bfloat16* __restrict__ Ah, const __nv_bfloat16* __restrict__ Al,
    const __nv_bfloat16* __restrict__ Bh, const __nv_bfloat16* __restrict__ Bl,
    const float* __restrict__ bias, int K, int N,
    float* __restrict__ Cf,
    __nv_bfloat16* __restrict__ Ch, __nv_bfloat16* __restrict__ Cl)
{
    extern __shared__ __align__(16) unsigned char SM[];

    const int tid  = threadIdx.x;
    const int wid  = tid >> 5;
    const int lane = tid & 31;
    const int g    = lane >> 2;
    const int t    = lane & 3;
    const int n0   = blockIdx.x * 128;
    const int m0   = blockIdx.y * 128;
    const int wm   = wid & 1;
    const int wn   = wid >> 1;
    const uint32_t smbase = smem_u32(SM);

    const int lrow = lane & 15;
    const int lkh  = lane >> 4;
    const int brow = lane & 7;
    const int bkh  = (lane >> 3) & 1;
    const int bts  = lane >> 4;

    float acc[4][4][4];
    #pragma unroll
    for (int i = 0; i < 4; i++)
        #pragma unroll
        for (int j = 0; j < 4; j++)
            #pragma unroll
            for (int q = 0; q < 4; q++) acc[i][j][q] = 0.f;

    auto issue_chunk = [&](int kbeg, int bsel) {
        uint32_t base = smbase + bsel * BUF_BYTES;
        #pragma unroll
        for (int i = 0; i < 8; i++) {
            int idx = tid + 256 * i;
            int sec = idx >> 9;
            int rem = idx & 511;
            int row = rem >> 2;
            int q   = rem & 3;
            const __nv_bfloat16* gsrc;
            if (sec == 0)      gsrc = Ah + (size_t)(m0 + row) * K + kbeg + q * 8;
            else if (sec == 1) gsrc = Al + (size_t)(m0 + row) * K + kbeg + q * 8;
            else if (sec == 2) gsrc = Bh + (size_t)(n0 + row) * K + kbeg + q * 8;
            else               gsrc = Bl + (size_t)(n0 + row) * K + kbeg + q * 8;
            uint32_t daddr = base + sec * SEC_BYTES + row * (SROW * 2) + q * 16;
            asm volatile("cp.async.cg.shared.global [%0], [%1], 16;"
                         :: "r"(daddr), "l"(gsrc));
        }
        asm volatile("cp.async.commit_group;" ::: "memory");
    };

    auto compute_chunk = [&](int bsel) {
        const uint32_t base = smbase + bsel * BUF_BYTES;
        #pragma unroll
        for (int ko = 0; ko < 32; ko += 16) {
            uint32_t ah[4][4], al[4][4], bh[4][2], bl[4][2];
            #pragma unroll
            for (int mt = 0; mt < 4; mt++) {
                uint32_t aoff = (wm * 64 + mt * 16 + lrow) * (SROW * 2) + (ko + 8 * lkh) * 2;
                LDSM_X4(ah[mt][0], ah[mt][1], ah[mt][2], ah[mt][3], base + aoff);
                LDSM_X4(al[mt][0], al[mt][1], al[mt][2], al[mt][3], base + SEC_BYTES + aoff);
            }
            #pragma unroll
            for (int p = 0; p < 2; p++) {
                uint32_t boff = (wn * 32 + p * 16 + bts * 8 + brow) * (SROW * 2) + (ko + 8 * bkh) * 2;
                LDSM_X4(bh[2*p][0], bh[2*p][1], bh[2*p+1][0], bh[2*p+1][1],
                        base + 2 * SEC_BYTES + boff);
                LDSM_X4(bl[2*p][0], bl[2*p][1], bl[2*p+1][0], bl[2*p+1][1],
                        base + 3 * SEC_BYTES + boff);
            }
            #pragma unroll
            for (int mt = 0; mt < 4; mt++)
                #pragma unroll
                for (int nt = 0; nt < 4; nt++)
                    MMA16816(acc[mt][nt], ah[mt], bh[nt]);
            #pragma unroll
            for (int mt = 0; mt < 4; mt++)
                #pragma unroll
                for (int nt = 0; nt < 4; nt++)
                    MMA16816(acc[mt][nt], ah[mt], bl[nt]);
            #pragma unroll
            for (int mt = 0; mt < 4; mt++)
                #pragma unroll
                for (int nt = 0; nt < 4; nt++)
                    MMA16816(acc[mt][nt], al[mt], bh[nt]);
        }
    };

    const int NC = K / 32;
    // 3-stage ring: 2 chunks in flight, one barrier per chunk
    issue_chunk(0, 0);
    issue_chunk(32, 1);
    int bsel = 0;
    for (int c = 0; c < NC; c++) {
        if (c == NC - 1) {
            asm volatile("cp.async.wait_group 0;" ::: "memory");
        } else {
            asm volatile("cp.async.wait_group 1;" ::: "memory");
        }
        __syncthreads();
        if (c + 2 < NC) {
            int nb = bsel + 2; if (nb >= 3) nb -= 3;
            issue_chunk((c + 2) * 32, nb);
        }
        compute_chunk(bsel);
        if (++bsel == 3) bsel = 0;
    }

    #pragma unroll
    for (int mt = 0; mt < 4; mt++) {
        const int m = m0 + wm * 64 + mt * 16 + g;
        #pragma unroll
        for (int nt = 0; nt < 4; nt++) {
            const int n = n0 + wn * 32 + nt * 8 + t * 2;
            float b0 = bias[n], b1 = bias[n + 1];
            float v00 = acc[mt][nt][0] + b0;
            float v01 = acc[mt][nt][1] + b1;
            float v10 = acc[mt][nt][2] + b0;
            float v11 = acc[mt][nt][3] + b1;
            v00 = (v00 > 0.f) ? v00 : 0.f;
            v01 = (v01 > 0.f) ? v01 : 0.f;
            v10 = (v10 > 0.f) ? v10 : 0.f;
            v11 = (v11 > 0.f) ? v11 : 0.f;
            if (HILO) {
                __nv_bfloat16 h00 = __float2bfloat16(v00);
                __nv_bfloat16 h01 = __float2bfloat16(v01);
                __nv_bfloat16 h10 = __float2bfloat16(v10);
                __nv_bfloat16 h11 = __float2bfloat16(v11);
                __nv_bfloat162 hp0; hp0.x = h00; hp0.y = h01;
                __nv_bfloat162 hp1; hp1.x = h10; hp1.y = h11;
                __nv_bfloat162 lp0;
                lp0.x = __float2bfloat16(v00 - __bfloat162float(h00));
                lp0.y = __float2bfloat16(v01 - __bfloat162float(h01));
                __nv_bfloat162 lp1;
                lp1.x = __float2bfloat16(v10 - __bfloat162float(h10));
                lp1.y = __float2bfloat16(v11 - __bfloat162float(h11));
                *(__nv_bfloat162*)(Ch + (size_t)m * N + n)       = hp0;
                *(__nv_bfloat162*)(Cl + (size_t)m * N + n)       = lp0;
                *(__nv_bfloat162*)(Ch + (size_t)(m + 8) * N + n) = hp1;
                *(__nv_bfloat162*)(Cl + (size_t)(m + 8) * N + n) = lp1;
            } else {
                float2 f0 = make_float2(v00, v01);
                float2 f1 = make_float2(v10, v11);
                *(float2*)(Cf + (size_t)m * N + n)       = f0;
                *(float2*)(Cf + (size_t)(m + 8) * N + n) = f1;
            }
        }
    }
}

// ---------------------------------------------------------------------------
// FC3 split-K GEMM (scalar) + reduce — unchanged
// ---------------------------------------------------------------------------
__global__ __launch_bounds__(256, 2) void fc3_splitk_kernel(
    const float* __restrict__ A,
    const float* __restrict__ Wr)
{
    __shared__ float As[2][8][128];
    __shared__ float Bs[2][8][32];

    const int tid = threadIdx.x;
    const int ks  = blockIdx.x;
    const int m0  = blockIdx.y * 128;
    const int kbeg = ks * (Hh / KSPLIT);
    const int tx = tid & 7;
    const int ty = tid >> 3;

    float acc[4][4];
    #pragma unroll
    for (int i = 0; i < 4; i++)
        #pragma unroll
        for (int j = 0; j < 4; j++) acc[i][j] = 0.f;

    const int r = tid >> 1;
    const int s = (tid & 1) * 4;
    const float* __restrict__ Arow = A + (size_t)(m0 + r) * Hh + kbeg + s;
    const float* __restrict__ Brow = Wr + (size_t)(tid >> 1) * Hh + kbeg + ((tid & 1) * 4);

    float4 a_n; float4 b_n = make_float4(0.f,0.f,0.f,0.f);

    a_n = *(const float4*)&Arow[0];
    if (tid < 64) b_n = *(const float4*)&Brow[0];
    As[0][s + 0][r] = a_n.x; As[0][s + 1][r] = a_n.y;
    As[0][s + 2][r] = a_n.z; As[0][s + 3][r] = a_n.w;
    if (tid < 64) {
        int bn = tid >> 1, bs = (tid & 1) * 4;
        Bs[0][bs + 0][bn] = b_n.x; Bs[0][bs + 1][bn] = b_n.y;
        Bs[0][bs + 2][bn] = b_n.z; Bs[0][bs + 3][bn] = b_n.w;
    }
    __syncthreads();

    int buf = 0;
    const int KC = Hh / KSPLIT;
    for (int k0 = 8; k0 <= KC; k0 += 8) {
        const bool more = (k0 < KC);
        if (more) {
            a_n = *(const float4*)&Arow[k0];
            if (tid < 64) b_n = *(const float4*)&Brow[k0];
        }

        #pragma unroll
        for (int k = 0; k < 8; k++) {
            float4 a0 = *(const float4*)&As[buf][k][ty * 4];
            float4 b0 = *(const float4*)&Bs[buf][k][tx * 4];
            float av[4] = {a0.x, a0.y, a0.z, a0.w};
            float bv[4] = {b0.x, b0.y, b0.z, b0.w};
            #pragma unroll
            for (int ii = 0; ii < 4; ii++)
                #pragma unroll
                for (int jj = 0; jj < 4; jj++)
                    acc[ii][jj] += av[ii] * bv[jj];
        }

        if (more) {
            int nb = buf ^ 1;
            As[nb][s + 0][r] = a_n.x; As[nb][s + 1][r] = a_n.y;
            As[nb][s + 2][r] = a_n.z; As[nb][s + 3][r] = a_n.w;
            if (tid < 64) {
                int bn = tid >> 1, bs = (tid & 1) * 4;
                Bs[nb][bs + 0][bn] = b_n.x; Bs[nb][bs + 1][bn] = b_n.y;
                Bs[nb][bs + 2][bn] = b_n.z; Bs[nb][bs + 3][bn] = b_n.w;
            }
            buf = nb;
            __syncthreads();
        }
    }

    float* __restrict__ part = (float*)g_fc3p + (size_t)ks * Pp * Rr;
    #pragma unroll
    for (int ii = 0; ii < 4; ii++) {
        int m = m0 + ty * 4 + ii;
        #pragma unroll
        for (int jj = 0; jj < 4; jj++) {
            int nn = tx * 4 + jj;
            part[(size_t)m * Rr + nn] = acc[ii][jj];
        }
    }
}

__global__ void fc3_reduce_kernel(const float* __restrict__ br,
                                  float* __restrict__ out)
{
    int i = blockIdx.x * blockDim.x + threadIdx.x;
    if (i < Pp * Rr) {
        const float* p = (const float*)g_fc3p;
        float v = p[i] + p[i + Pp*Rr] + p[i + 2*Pp*Rr] + p[i + 3*Pp*Rr];
        out[i] = v + br[i & (Rr - 1)];
    }
}

// ---------------------------------------------------------------------------
__global__ void pack_kernel(const float* __restrict__ trig,
                            const int* __restrict__ labels,
                            float* __restrict__ out, int out_size)
{
    int i = blockIdx.x * blockDim.x + threadIdx.x;
    const int PR = Pp * Rr;
    const int BT = Bb * Tt;
    if (out_size >= PR + BT && i < BT)        out[PR + i]      = trig[i];
    if (out_size >= PR + BT + Pp && i < Pp)   out[PR + BT + i] = (float)labels[i];
}

// ---------------------------------------------------------------------------
extern "C" void kernel_launch(void* const* d_in, const int* in_sizes, int n_in,
                              void* d_out, int out_size)
{
    const float* x     = (const float*)d_in[0];
    const float* trig  = (const float*)d_in[1];
    const int*   bidx  = (const int*)  d_in[2];
    const int*   hidx  = (const int*)  d_in[3];
    const int*   hspan = (const int*)  d_in[4];
    const int*   tidx  = (const int*)  d_in[5];
    const int*   tspan = (const int*)  d_in[6];
    const int*   labels= (const int*)  d_in[7];
    const float* c1w   = (const float*)d_in[8];
    const float* c1b   = (const float*)d_in[9];
    const float* c2w   = (const float*)d_in[10];
    const float* c2b   = (const float*)d_in[11];
    const float* w1    = (const float*)d_in[12];
    const float* b1    = (const float*)d_in[13];
    const float* w2    = (const float*)d_in[14];
    const float* b2    = (const float*)d_in[15];
    const float* wr    = (const float*)d_in[16];
    const float* br    = (const float*)d_in[17];
    float* out = (float*)d_out;

    __nv_bfloat16 *pxh, *pxl, *px1h, *px1l, *pwt1h, *pwt1l, *pwt2h, *pwt2l;
    __nv_bfloat16 *pmxh, *pmxl, *pw1h, *pw1l, *pw2h, *pw2l, *ph1h, *ph1l;
    float *px1, *pxbte, *ph2;
    cudaGetSymbolAddress((void**)&pxh,   g_xh);
    cudaGetSymbolAddress((void**)&pxl,   g_xl);
    cudaGetSymbolAddress((void**)&px1h,  g_x1h);
    cudaGetSymbolAddress((void**)&px1l,  g_x1l);
    cudaGetSymbolAddress((void**)&pwt1h, g_wt1h);
    cudaGetSymbolAddress((void**)&pwt1l, g_wt1l);
    cudaGetSymbolAddress((void**)&pwt2h, g_wt2h);
    cudaGetSymbolAddress((void**)&pwt2l, g_wt2l);
    cudaGetSymbolAddress((void**)&pmxh,  g_mx_h);
    cudaGetSymbolAddress((void**)&pmxl,  g_mx_l);
    cudaGetSymbolAddress((void**)&pw1h,  g_w1h);
    cudaGetSymbolAddress((void**)&pw1l,  g_w1l);
    cudaGetSymbolAddress((void**)&pw2h,  g_w2h);
    cudaGetSymbolAddress((void**)&pw2l,  g_w2l);
    cudaGetSymbolAddress((void**)&ph1h,  g_h1h);
    cudaGetSymbolAddress((void**)&ph1l,  g_h1l);
    cudaGetSymbolAddress((void**)&px1,   g_x1);
    cudaGetSymbolAddress((void**)&pxbte, g_xbte);
    cudaGetSymbolAddress((void**)&ph2,   g_h2);

    static int smem_set = 0;
    if (!smem_set) {
        cudaFuncSetAttribute(fc_mma_kernel<true>,
                             cudaFuncAttributeMaxDynamicSharedMemorySize, FC_SMEM);
        cudaFuncSetAttribute(fc_mma_kernel<false>,
                             cudaFuncAttributeMaxDynamicSharedMemorySize, FC_SMEM);
        cudaFuncSetAttribute(conv_mma_kernel<0>,
                             cudaFuncAttributeMaxDynamicSharedMemorySize, CONV_SMEM);
        cudaFuncSetAttribute(conv_mma_kernel<1>,
                             cudaFuncAttributeMaxDynamicSharedMemorySize, CONV_SMEM);
        smem_set = 1;
    }

    // Conversions
    {
        dim3 tg(Tt / 32, Ee / 32, Bb);
        cvt_transpose_kernel<<<tg, 256>>>(x, pxh, pxl);   // x -> hi/lo (B,T,E)
    }
    cvt_wt_kernel<<<(Ee*Ee*3 + 255)/256, 256>>>(c1w, pwt1h, pwt1l);
    cvt_wt_kernel<<<(Ee*Ee*3 + 255)/256, 256>>>(c2w, pwt2h, pwt2l);
    cvt_hilo_kernel<<<(Hh*Ee + 255)/256, 256>>>(w1, pw1h, pw1l, Hh*Ee);
    cvt_hilo_kernel<<<(Hh*Hh + 255)/256, 256>>>(w2, pw2h, pw2l, Hh*Hh);

    // Conv blocks (tensor cores, fully async loads)
    {
        dim3 grid((Bb * Tt) / 128, Ee / 128);
        conv_mma_kernel<0><<<grid, 256, CONV_SMEM>>>(
            pxh, pxl, pwt1h, pwt1l, c1b, x, px1, px1h, px1l);
        conv_mma_kernel<1><<<grid, 256, CONV_SMEM>>>(
            px1h, px1l, pwt2h, pwt2l, c2b, px1, pxbte, nullptr, nullptr);
    }

    // Span max -> bf16 hi/lo
    span_kernel<<<Pp, 128>>>(bidx, hidx, hspan, tidx, tspan);

    // FC1 (mma bf16x3): (P,512)x(1024,512)^T -> h1 hi/lo, relu
    {
        dim3 grid(Hh / 128, Pp / 128);
        fc_mma_kernel<true><<<grid, 256, FC_SMEM>>>(
            pmxh, pmxl, pw1h, pw1l, b1, Ee, Hh, nullptr, ph1h, ph1l);
    }
    // FC2 (mma bf16x3): (P,1024)x(1024,1024)^T -> h2 fp32, relu
    {
        dim3 grid(Hh / 128, Pp / 128);
        fc_mma_kernel<false><<<grid, 256, FC_SMEM>>>(
            ph1h, ph1l, pw2h, pw2l, b2, Hh, Hh, ph2, nullptr, nullptr);
    }
    // FC3: split-K + reduce into d_out
    {
        dim3 grid(KSPLIT, Pp / 128);
        fc3_splitk_kernel<<<grid, 256>>>(ph2, wr);
        fc3_reduce_kernel<<<(Pp * Rr + 255) / 256, 256>>>(br, out);
    }
    // trig_attn + rel_labels passthrough
    pack_kernel<<<(8192 + 255) / 256, 256>>>(trig, labels, out, out_size);
}

// round 15
// speedup vs baseline: 1.0318x; 1.0318x over previous
#include <cuda_runtime.h>
#include <cuda_bf16.h>
#include <math.h>
#include <stdint.h>

// Problem constants
#define Bb 16
#define Ee 512
#define Tt 512
#define Hh 1024
#define Rr 32
#define Pp 8192
#define Ww 3
#define KSPLIT 4

// bf16 m16n8k16 tensor-core MMA (baseline PTX, valid on sm_103)
#define MMA16816(C, A, B) \
    asm volatile("mma.sync.aligned.m16n8k16.row.col.f32.bf16.bf16.f32 " \
        "{%0,%1,%2,%3}, {%4,%5,%6,%7}, {%8,%9}, {%0,%1,%2,%3};" \
        : "+f"((C)[0]), "+f"((C)[1]), "+f"((C)[2]), "+f"((C)[3]) \
        : "r"((A)[0]), "r"((A)[1]), "r"((A)[2]), "r"((A)[3]), \
          "r"((B)[0]), "r"((B)[1]))

#define LDSM_X4(R0, R1, R2, R3, addr) \
    asm volatile("ldmatrix.sync.aligned.m8n8.x4.shared.b16 {%0,%1,%2,%3}, [%4];" \
        : "=r"(R0), "=r"(R1), "=r"(R2), "=r"(R3) : "r"(addr))

__device__ __forceinline__ uint32_t smem_u32(const void* p) {
    uint32_t a;
    asm("{ .reg .u64 t; cvta.to.shared.u64 t, %1; cvt.u32.u64 %0, t; }" : "=r"(a) : "l"(p));
    return a;
}

// Scratch (device globals: allocation-free per harness rules)
__device__ float g_x1[Bb*Ee*Tt];                 // conv1 out fp32 (B,E,T)
__device__ float g_xbte[Bb*Tt*Ee];               // conv2 out fp32 (B,T,E)
__device__ __nv_bfloat16 g_xh[Bb*Tt*Ee];         // input x hi/lo (B,T,E) !
__device__ __nv_bfloat16 g_xl[Bb*Tt*Ee];
__device__ __nv_bfloat16 g_x1h[Bb*Tt*Ee];        // conv1 out hi/lo (B,T,E) !
__device__ __nv_bfloat16 g_x1l[Bb*Tt*Ee];
__device__ __nv_bfloat16 g_wt1h[3*Ee*Ee];        // conv weights [dk][eo][ei]
__device__ __nv_bfloat16 g_wt1l[3*Ee*Ee];
__device__ __nv_bfloat16 g_wt2h[3*Ee*Ee];
__device__ __nv_bfloat16 g_wt2l[3*Ee*Ee];
__device__ __nv_bfloat16 g_mx_h[Pp*Ee];
__device__ __nv_bfloat16 g_mx_l[Pp*Ee];
__device__ __nv_bfloat16 g_w1h[Hh*Ee];
__device__ __nv_bfloat16 g_w1l[Hh*Ee];
__device__ __nv_bfloat16 g_w2h[Hh*Hh];
__device__ __nv_bfloat16 g_w2l[Hh*Hh];
__device__ __nv_bfloat16 g_h1h[Pp*Hh];
__device__ __nv_bfloat16 g_h1l[Pp*Hh];
__device__ float g_h2[Pp*Hh];
__device__ float g_fc3p[KSPLIT*Pp*Rr];

// fp32 -> bf16 hi/lo (elementwise, for FC weights)
__global__ void cvt_hilo_kernel(const float* __restrict__ in,
                                __nv_bfloat16* __restrict__ hi,
                                __nv_bfloat16* __restrict__ lo, int n)
{
    int i = blockIdx.x * blockDim.x + threadIdx.x;
    if (i < n) {
        float x = in[i];
        __nv_bfloat16 h = __float2bfloat16(x);
        hi[i] = h;
        lo[i] = __float2bfloat16(x - __bfloat162float(h));
    }
}

// fp32 (B,E,T) -> bf16 hi/lo (B,T,E), 32x32 smem transpose
__global__ __launch_bounds__(256) void cvt_transpose_kernel(
    const float* __restrict__ in,
    __nv_bfloat16* __restrict__ hi,
    __nv_bfloat16* __restrict__ lo)
{
    __shared__ float tile[32][33];
    const int b  = blockIdx.z;
    const int e0 = blockIdx.y * 32;
    const int t0 = blockIdx.x * 32;
    const int tx = threadIdx.x & 31;
    const int ty = threadIdx.x >> 5;    // 0..7

    #pragma unroll
    for (int r = ty; r < 32; r += 8)
        tile[r][tx] = in[((size_t)b * Ee + e0 + r) * Tt + t0 + tx];
    __syncthreads();
    #pragma unroll
    for (int r = ty; r < 32; r += 8) {
        float v = tile[tx][r];          // (e_local=tx, t_local=r)
        __nv_bfloat16 h = __float2bfloat16(v);
        size_t o = ((size_t)b * Tt + t0 + r) * Ee + e0 + tx;
        hi[o] = h;
        lo[o] = __float2bfloat16(v - __bfloat162float(h));
    }
}

// conv weights (eo,ei,dk) -> transposed [dk][eo][ei] hi/lo
__global__ void cvt_wt_kernel(const float* __restrict__ w,
                              __nv_bfloat16* __restrict__ th,
                              __nv_bfloat16* __restrict__ tl)
{
    int i = blockIdx.x * blockDim.x + threadIdx.x;
    if (i < Ee * Ee * 3) {
        int eo  = i / (Ee * 3);
        int rem = i - eo * (Ee * 3);
        int ei  = rem / 3;
        int dk  = rem - ei * 3;
        float x = w[i];
        __nv_bfloat16 h = __float2bfloat16(x);
        int o = dk * (Ee * Ee) + eo * Ee + ei;
        th[o] = h;
        tl[o] = __float2bfloat16(x - __bfloat162float(h));
    }
}

// ---------------------------------------------------------------------------
// Conv residual block via mma.sync bf16x3 + ldmatrix; B via cp.async from
// (B,T,E)-layout hi/lo (fully async loads). Double-buffered.
// MODE 0: write g_x1 fp32 (B,E,T) + g_x1h/l bf16 (B,T,E)
// MODE 1: write g_xbte fp32 (B,T,E)
// ---------------------------------------------------------------------------
#define CROWB 80
#define CAH 0
#define CAL (384*CROWB)
#define CBH (2*384*CROWB)
#define CBL (CBH + 130*CROWB)
#define CBUF (CBL + 130*CROWB)
#define CONV_SMEM (2*CBUF)

template<int MODE>
__global__ __launch_bounds__(256, 1) void conv_mma_kernel(
    const __nv_bfloat16* __restrict__ xh_g, const __nv_bfloat16* __restrict__ xl_g,
    const __nv_bfloat16* __restrict__ wth,  const __nv_bfloat16* __restrict__ wtl,
    const float* __restrict__ bias, const float* __restrict__ resid,
    float* __restrict__ outf,
    __nv_bfloat16* __restrict__ outh, __nv_bfloat16* __restrict__ outl)
{
    extern __shared__ __align__(16) unsigned char SM[];

    const int tid  = threadIdx.x;
    const int wid  = tid >> 5;
    const int lane = tid & 31;
    const int g    = lane >> 2;
    const int tq   = lane & 3;
    const int n0   = blockIdx.x * 128;
    const int m0   = blockIdx.y * 128;
    const int b    = n0 >> 9;
    const int t0   = n0 & 511;
    const int wm   = wid & 1;
    const int wn   = wid >> 1;
    const uint32_t smbase = smem_u32(SM);

    const int lrow = lane & 15;
    const int lkh  = lane >> 4;
    const int brow = lane & 7;
    const int bkh  = (lane >> 3) & 1;
    const int bts  = lane >> 4;

    // (B,T,E) layout
    const __nv_bfloat16* __restrict__ xh_b = xh_g + (size_t)b * Tt * Ee;
    const __nv_bfloat16* __restrict__ xl_b = xl_g + (size_t)b * Tt * Ee;

    float acc[4][4][4];
    #pragma unroll
    for (int i = 0; i < 4; i++)
        #pragma unroll
        for (int j = 0; j < 4; j++)
            #pragma unroll
            for (int q = 0; q < 4; q++) acc[i][j][q] = 0.f;

    // ---- chunk loader: all cp.async ----
    auto issue = [&](int kbeg, int bsel) {
        uint32_t base = smbase + bsel * CBUF;
        unsigned char* bb = SM + bsel * CBUF;
        // A: weights, 3 taps x 128 eo x 32 ei, hi+lo = 3072 x 16B, 12/thread
        #pragma unroll
        for (int i = 0; i < 12; i++) {
            int idx = tid + 256 * i;
            int hl  = (idx >= 1536);
            int r   = hl ? (idx - 1536) : idx;
            int row = r >> 2;
            int q   = r & 3;
            int dk  = row >> 7;
            int eo  = row & 127;
            const __nv_bfloat16* gsrc =
                (hl ? wtl : wth) + (size_t)dk * (Ee * Ee) + (size_t)(m0 + eo) * Ee + kbeg + q * 8;
            uint32_t daddr = base + (hl ? CAL : CAH) + row * CROWB + q * 16;
            asm volatile("cp.async.cg.shared.global [%0], [%1], 16;"
                         :: "r"(daddr), "l"(gsrc));
        }
        // B: x (B,T,E): 130 rows (t0-1..t0+128) x 32 ei (64B = 4x16B), hi+lo
        // 1040 units, 5 iters with guard
        #pragma unroll
        for (int i = 0; i < 5; i++) {
            int idx = tid + 256 * i;
            if (idx < 1040) {
                int hl  = (idx >= 520);
                int r   = hl ? (idx - 520) : idx;
                int row = r >> 2;          // 0..129, global t = t0-1+row
                int u   = r & 3;
                int t   = t0 - 1 + row;
                uint32_t off = (hl ? CBL : CBH) + row * CROWB + u * 16;
                if ((unsigned)t < (unsigned)Tt) {
                    const __nv_bfloat16* gsrc =
                        (hl ? xl_b : xh_b) + (size_t)t * Ee + kbeg + u * 8;
                    asm volatile("cp.async.cg.shared.global [%0], [%1], 16;"
                                 :: "r"(base + off), "l"(gsrc));
                } else {
                    *(uint4*)(bb + off) = make_uint4(0, 0, 0, 0);
                }
            }
        }
        asm volatile("cp.async.commit_group;" ::: "memory");
    };

    // ---- compute one K=32 chunk (ldmatrix) ----
    auto compute = [&](int bsel) {
        const uint32_t base = smbase + bsel * CBUF;
        #pragma unroll
        for (int ko = 0; ko < 32; ko += 16) {
            #pragma unroll
            for (int dk = 0; dk < 3; dk++) {
                uint32_t ah[4][4], al[4][4], bh[4][2], bl[4][2];
                #pragma unroll
                for (int mt = 0; mt < 4; mt++) {
                    int row = dk * 128 + wm * 64 + mt * 16 + lrow;
                    uint32_t aoff = row * CROWB + (ko + 8 * lkh) * 2;
                    LDSM_X4(ah[mt][0], ah[mt][1], ah[mt][2], ah[mt][3], base + CAH + aoff);
                    LDSM_X4(al[mt][0], al[mt][1], al[mt][2], al[mt][3], base + CAL + aoff);
                }
                #pragma unroll
                for (int p = 0; p < 2; p++) {
                    int row = wn * 32 + p * 16 + bts * 8 + brow + dk;
                    uint32_t boff = row * CROWB + (ko + 8 * bkh) * 2;
                    LDSM_X4(bh[2*p][0], bh[2*p][1], bh[2*p+1][0], bh[2*p+1][1], base + CBH + boff);
                    LDSM_X4(bl[2*p][0], bl[2*p][1], bl[2*p+1][0], bl[2*p+1][1], base + CBL + boff);
                }
                #pragma unroll
                for (int mt = 0; mt < 4; mt++)
                    #pragma unroll
                    for (int nt = 0; nt < 4; nt++)
                        MMA16816(acc[mt][nt], ah[mt], bh[nt]);
                #pragma unroll
                for (int mt = 0; mt < 4; mt++)
                    #pragma unroll
                    for (int nt = 0; nt < 4; nt++)
                        MMA16816(acc[mt][nt], ah[mt], bl[nt]);
                #pragma unroll
                for (int mt = 0; mt < 4; mt++)
                    #pragma unroll
                    for (int nt = 0; nt < 4; nt++)
                        MMA16816(acc[mt][nt], al[mt], bh[nt]);
            }
        }
    };

    const int NC = Ee / 32;
    issue(0, 0);
    for (int c = 0; c < NC; c++) {
        if (c + 1 < NC) {
            issue((c + 1) * 32, (c + 1) & 1);
            asm volatile("cp.async.wait_group 1;" ::: "memory");
        } else {
            asm volatile("cp.async.wait_group 0;" ::: "memory");
        }
        __syncthreads();
        compute(c & 1);
        __syncthreads();
    }

    // ---- epilogue ----
    #pragma unroll
    for (int mt = 0; mt < 4; mt++) {
        const int eo0 = m0 + wm * 64 + mt * 16 + g;
        const int eo1 = eo0 + 8;
        const float b0v = bias[eo0], b1v = bias[eo1];
        #pragma unroll
        for (int nt = 0; nt < 4; nt++) {
            const int n = t0 + wn * 32 + nt * 8 + tq * 2;
            float v00 = acc[mt][nt][0] + b0v;
            float v01 = acc[mt][nt][1] + b0v;
            float v10 = acc[mt][nt][2] + b1v;
            float v11 = acc[mt][nt][3] + b1v;
            v00 = (v00 > 0.f) ? v00 : 0.f;
            v01 = (v01 > 0.f) ? v01 : 0.f;
            v10 = (v10 > 0.f) ? v10 : 0.f;
            v11 = (v11 > 0.f) ? v11 : 0.f;
            size_t i00 = ((size_t)b * Ee + eo0) * Tt + n;
            size_t i10 = ((size_t)b * Ee + eo1) * Tt + n;
            v00 += resid[i00];     v01 += resid[i00 + 1];
            v10 += resid[i10];     v11 += resid[i10 + 1];
            if (MODE == 0) {
                outf[i00] = v00; outf[i00 + 1] = v01;
                outf[i10] = v10; outf[i10 + 1] = v11;
                // hi/lo to (B,T,E) for conv2's async B loads
                size_t j00 = ((size_t)b * Tt + n) * Ee + eo0;  // (t=n, eo0)
                __nv_bfloat16 h00 = __float2bfloat16(v00);
                __nv_bfloat16 h01 = __float2bfloat16(v01);
                __nv_bfloat16 h10 = __float2bfloat16(v10);
                __nv_bfloat16 h11 = __float2bfloat16(v11);
                outh[j00]          = h00;
                outh[j00 + Ee]     = h01;
                outh[j00 + 8]      = h10;
                outh[j00 + Ee + 8] = h11;
                outl[j00]          = __float2bfloat16(v00 - __bfloat162float(h00));
                outl[j00 + Ee]     = __float2bfloat16(v01 - __bfloat162float(h01));
                outl[j00 + 8]      = __float2bfloat16(v10 - __bfloat162float(h10));
                outl[j00 + Ee + 8] = __float2bfloat16(v11 - __bfloat162float(h11));
            } else {
                outf[((size_t)b * Tt + n)     * Ee + eo0] = v00;
                outf[((size_t)b * Tt + n + 1) * Ee + eo0] = v01;
                outf[((size_t)b * Tt + n)     * Ee + eo1] = v10;
                outf[((size_t)b * Tt + n + 1) * Ee + eo1] = v11;
            }
        }
    }
}

// ---------------------------------------------------------------------------
// Span max gather -> bf16 hi/lo
// ---------------------------------------------------------------------------
__global__ __launch_bounds__(128) void span_kernel(
    const int* __restrict__ bidx,
    const int* __restrict__ hidx, const int* __restrict__ hspan,
    const int* __restrict__ tidx, const int* __restrict__ tspan)
{
    const int p  = blockIdx.x;
    const int e4 = threadIdx.x;
    const int b  = bidx[p];
    const float4* __restrict__ base = (const float4*)g_xbte + (size_t)b * Tt * (Ee / 4);

    const int h0 = hidx[p], hs = hspan[p];
    const int t0 = tidx[p], ts = tspan[p];

    float4 hm = make_float4(-INFINITY, -INFINITY, -INFINITY, -INFINITY);
    for (int s = 0; s < hs; s++) {
        float4 v = base[(size_t)(h0 + s) * (Ee / 4) + e4];
        hm.x = fmaxf(hm.x, v.x); hm.y = fmaxf(hm.y, v.y);
        hm.z = fmaxf(hm.z, v.z); hm.w = fmaxf(hm.w, v.w);
    }
    float4 tm = make_float4(-INFINITY, -INFINITY, -INFINITY, -INFINITY);
    for (int s = 0; s < ts; s++) {
        float4 v = base[(size_t)(t0 + s) * (Ee / 4) + e4];
        tm.x = fmaxf(tm.x, v.x); tm.y = fmaxf(tm.y, v.y);
        tm.z = fmaxf(tm.z, v.z); tm.w = fmaxf(tm.w, v.w);
    }
    float o[4] = {hm.x + tm.x, hm.y + tm.y, hm.z + tm.z, hm.w + tm.w};

    size_t off = (size_t)p * Ee + e4 * 4;
    #pragma unroll
    for (int j = 0; j < 4; j++) {
        __nv_bfloat16 h = __float2bfloat16(o[j]);
        __nv_bfloat16 l = __float2bfloat16(o[j] - __bfloat162float(h));
        g_mx_h[off + j] = h;
        g_mx_l[off + j] = l;
    }
}

// ---------------------------------------------------------------------------
// Tensor-core bf16x3 NT GEMM (FC1/FC2): ldmatrix + 3-stage cp.async ring,
// single __syncthreads per chunk.
// ---------------------------------------------------------------------------
#define SROW 40
#define SEC_ELEMS (128*SROW)
#define SEC_BYTES (SEC_ELEMS*2)
#define BUF_BYTES (4*SEC_BYTES)
#define FC_SMEM   (3*BUF_BYTES)

template<bool HILO>
__global__ __launch_bounds__(256, 1) void fc_mma_kernel(
    const __nv_bfloat16* __restrict__ Ah, const __nv_bfloat16* __restrict__ Al,
    const __nv_bfloat16* __restrict__ Bh, const __nv_bfloat16* __restrict__ Bl,
    const float* __restrict__ bias, int K, int N,
    float* __restrict__ Cf,
    __nv_bfloat16* __restrict__ Ch, __nv_bfloat16* __restrict__ Cl)
{
    extern __shared__ __align__(16) unsigned char SM[];

    const int tid  = threadIdx.x;
    const int wid  = tid >> 5;
    const int lane = tid & 31;
    const int g    = lane >> 2;
    const int t    = lane & 3;
    const int n0   = blockIdx.x * 128;
    const int m0   = blockIdx.y * 128;
    const int wm   = wid & 1;
    const int wn   = wid >> 1;
    const uint32_t smbase = smem_u32(SM);

    const int lrow = lane & 15;
    const int lkh  = lane >> 4;
    const int brow = lane & 7;
    const int bkh  = (lane >> 3) & 1;
    const int bts  = lane >> 4;

    float acc[4][4][4];
    #pragma unroll
    for (int i = 0; i < 4; i++)
        #pragma unroll
        for (int j = 0; j < 4; j++)
            #pragma unroll
            for (int q = 0; q < 4; q++) acc[i][j][q] = 0.f;

    auto issue_chunk = [&](int kbeg, int bsel) {
        uint32_t base = smbase + bsel * BUF_BYTES;
        #pragma unroll
        for (int i = 0; i < 8; i++) {
            int idx = tid + 256 * i;
            int sec = idx >> 9;
            int rem = idx & 511;
            int row = rem >> 2;
            int q   = rem & 3;
            const __nv_bfloat16* gsrc;
            if (sec == 0)      gsrc = Ah + (size_t)(m0 + row) * K + kbeg + q * 8;
            else if (sec == 1) gsrc = Al + (size_t)(m0 + row) * K + kbeg + q * 8;
            else if (sec == 2) gsrc = Bh + (size_t)(n0 + row) * K + kbeg + q * 8;
            else               gsrc = Bl + (size_t)(n0 + row) * K + kbeg + q * 8;
            uint32_t daddr = base + sec * SEC_BYTES + row * (SROW * 2) + q * 16;
            asm volatile("cp.async.cg.shared.global [%0], [%1], 16;"
                         :: "r"(daddr), "l"(gsrc));
        }
        asm volatile("cp.async.commit_group;" ::: "memory");
    };

    auto compute_chunk = [&](int bsel) {
        const uint32_t base = smbase + bsel * BUF_BYTES;
        #pragma unroll
        for (int ko = 0; ko < 32; ko += 16) {
            uint32_t ah[4][4], al[4][4], bh[4][2], bl[4][2];
            #pragma unroll
            for (int mt = 0; mt < 4; mt++) {
                uint32_t aoff = (wm * 64 + mt * 16 + lrow) * (SROW * 2) + (ko + 8 * lkh) * 2;
                LDSM_X4(ah[mt][0], ah[mt][1], ah[mt][2], ah[mt][3], base + aoff);
                LDSM_X4(al[mt][0], al[mt][1], al[mt][2], al[mt][3], base + SEC_BYTES + aoff);
            }
            #pragma unroll
            for (int p = 0; p < 2; p++) {
                uint32_t boff = (wn * 32 + p * 16 + bts * 8 + brow) * (SROW * 2) + (ko + 8 * bkh) * 2;
                LDSM_X4(bh[2*p][0], bh[2*p][1], bh[2*p+1][0], bh[2*p+1][1],
                        base + 2 * SEC_BYTES + boff);
                LDSM_X4(bl[2*p][0], bl[2*p][1], bl[2*p+1][0], bl[2*p+1][1],
                        base + 3 * SEC_BYTES + boff);
            }
            #pragma unroll
            for (int mt = 0; mt < 4; mt++)
                #pragma unroll
                for (int nt = 0; nt < 4; nt++)
                    MMA16816(acc[mt][nt], ah[mt], bh[nt]);
            #pragma unroll
            for (int mt = 0; mt < 4; mt++)
                #pragma unroll
                for (int nt = 0; nt < 4; nt++)
                    MMA16816(acc[mt][nt], ah[mt], bl[nt]);
            #pragma unroll
            for (int mt = 0; mt < 4; mt++)
                #pragma unroll
                for (int nt = 0; nt < 4; nt++)
                    MMA16816(acc[mt][nt], al[mt], bh[nt]);
        }
    };

    const int NC = K / 32;
    // 3-stage ring: 2 chunks in flight, one barrier per chunk
    issue_chunk(0, 0);
    issue_chunk(32, 1);
    int bsel = 0;
    for (int c = 0; c < NC; c++) {
        if (c == NC - 1) {
            asm volatile("cp.async.wait_group 0;" ::: "memory");
        } else {
            asm volatile("cp.async.wait_group 1;" ::: "memory");
        }
        __syncthreads();
        if (c + 2 < NC) {
            int nb = bsel + 2; if (nb >= 3) nb -= 3;
            issue_chunk((c + 2) * 32, nb);
        }
        compute_chunk(bsel);
        if (++bsel == 3) bsel = 0;
    }

    #pragma unroll
    for (int mt = 0; mt < 4; mt++) {
        const int m = m0 + wm * 64 + mt * 16 + g;
        #pragma unroll
        for (int nt = 0; nt < 4; nt++) {
            const int n = n0 + wn * 32 + nt * 8 + t * 2;
            float b0 = bias[n], b1 = bias[n + 1];
            float v00 = acc[mt][nt][0] + b0;
            float v01 = acc[mt][nt][1] + b1;
            float v10 = acc[mt][nt][2] + b0;
            float v11 = acc[mt][nt][3] + b1;
            v00 = (v00 > 0.f) ? v00 : 0.f;
            v01 = (v01 > 0.f) ? v01 : 0.f;
            v10 = (v10 > 0.f) ? v10 : 0.f;
            v11 = (v11 > 0.f) ? v11 : 0.f;
            if (HILO) {
                __nv_bfloat16 h00 = __float2bfloat16(v00);
                __nv_bfloat16 h01 = __float2bfloat16(v01);
                __nv_bfloat16 h10 = __float2bfloat16(v10);
                __nv_bfloat16 h11 = __float2bfloat16(v11);
                __nv_bfloat162 hp0; hp0.x = h00; hp0.y = h01;
                __nv_bfloat162 hp1; hp1.x = h10; hp1.y = h11;
                __nv_bfloat162 lp0;
                lp0.x = __float2bfloat16(v00 - __bfloat162float(h00));
                lp0.y = __float2bfloat16(v01 - __bfloat162float(h01));
                __nv_bfloat162 lp1;
                lp1.x = __float2bfloat16(v10 - __bfloat162float(h10));
                lp1.y = __float2bfloat16(v11 - __bfloat162float(h11));
                *(__nv_bfloat162*)(Ch + (size_t)m * N + n)       = hp0;
                *(__nv_bfloat162*)(Cl + (size_t)m * N + n)       = lp0;
                *(__nv_bfloat162*)(Ch + (size_t)(m + 8) * N + n) = hp1;
                *(__nv_bfloat162*)(Cl + (size_t)(m + 8) * N + n) = lp1;
            } else {
                float2 f0 = make_float2(v00, v01);
                float2 f1 = make_float2(v10, v11);
                *(float2*)(Cf + (size_t)m * N + n)       = f0;
                *(float2*)(Cf + (size_t)(m + 8) * N + n) = f1;
            }
        }
    }
}

// ---------------------------------------------------------------------------
// FC3 split-K GEMM (scalar) + reduce — unchanged
// ---------------------------------------------------------------------------
__global__ __launch_bounds__(256, 2) void fc3_splitk_kernel(
    const float* __restrict__ A,
    const float* __restrict__ Wr)
{
    __shared__ float As[2][8][128];
    __shared__ float Bs[2][8][32];

    const int tid = threadIdx.x;
    const int ks  = blockIdx.x;
    const int m0  = blockIdx.y * 128;
    const int kbeg = ks * (Hh / KSPLIT);
    const int tx = tid & 7;
    const int ty = tid >> 3;

    float acc[4][4];
    #pragma unroll
    for (int i = 0; i < 4; i++)
        #pragma unroll
        for (int j = 0; j < 4; j++) acc[i][j] = 0.f;

    const int r = tid >> 1;
    const int s = (tid & 1) * 4;
    const float* __restrict__ Arow = A + (size_t)(m0 + r) * Hh + kbeg + s;
    const float* __restrict__ Brow = Wr + (size_t)(tid >> 1) * Hh + kbeg + ((tid & 1) * 4);

    float4 a_n; float4 b_n = make_float4(0.f,0.f,0.f,0.f);

    a_n = *(const float4*)&Arow[0];
    if (tid < 64) b_n = *(const float4*)&Brow[0];
    As[0][s + 0][r] = a_n.x; As[0][s + 1][r] = a_n.y;
    As[0][s + 2][r] = a_n.z; As[0][s + 3][r] = a_n.w;
    if (tid < 64) {
        int bn = tid >> 1, bs = (tid & 1) * 4;
        Bs[0][bs + 0][bn] = b_n.x; Bs[0][bs + 1][bn] = b_n.y;
        Bs[0][bs + 2][bn] = b_n.z; Bs[0][bs + 3][bn] = b_n.w;
    }
    __syncthreads();

    int buf = 0;
    const int KC = Hh / KSPLIT;
    for (int k0 = 8; k0 <= KC; k0 += 8) {
        const bool more = (k0 < KC);
        if (more) {
            a_n = *(const float4*)&Arow[k0];
            if (tid < 64) b_n = *(const float4*)&Brow[k0];
        }

        #pragma unroll
        for (int k = 0; k < 8; k++) {
            float4 a0 = *(const float4*)&As[buf][k][ty * 4];
            float4 b0 = *(const float4*)&Bs[buf][k][tx * 4];
            float av[4] = {a0.x, a0.y, a0.z, a0.w};
            float bv[4] = {b0.x, b0.y, b0.z, b0.w};
            #pragma unroll
            for (int ii = 0; ii < 4; ii++)
                #pragma unroll
                for (int jj = 0; jj < 4; jj++)
                    acc[ii][jj] += av[ii] * bv[jj];
        }

        if (more) {
            int nb = buf ^ 1;
            As[nb][s + 0][r] = a_n.x; As[nb][s + 1][r] = a_n.y;
            As[nb][s + 2][r] = a_n.z; As[nb][s + 3][r] = a_n.w;
            if (tid < 64) {
                int bn = tid >> 1, bs = (tid & 1) * 4;
                Bs[nb][bs + 0][bn] = b_n.x; Bs[nb][bs + 1][bn] = b_n.y;
                Bs[nb][bs + 2][bn] = b_n.z; Bs[nb][bs + 3][bn] = b_n.w;
            }
            buf = nb;
            __syncthreads();
        }
    }

    float* __restrict__ part = (float*)g_fc3p + (size_t)ks * Pp * Rr;
    #pragma unroll
    for (int ii = 0; ii < 4; ii++) {
        int m = m0 + ty * 4 + ii;
        #pragma unroll
        for (int jj = 0; jj < 4; jj++) {
            int nn = tx * 4 + jj;
            part[(size_t)m * Rr + nn] = acc[ii][jj];
        }
    }
}

__global__ void fc3_reduce_kernel(const float* __restrict__ br,
                                  float* __restrict__ out)
{
    int i = blockIdx.x * blockDim.x + threadIdx.x;
    if (i < Pp * Rr) {
        const float* p = (const float*)g_fc3p;
        float v = p[i] + p[i + Pp*Rr] + p[i + 2*Pp*Rr] + p[i + 3*Pp*Rr];
        out[i] = v + br[i & (Rr - 1)];
    }
}

// ---------------------------------------------------------------------------
__global__ void pack_kernel(const float* __restrict__ trig,
                            const int* __restrict__ labels,
                            float* __restrict__ out, int out_size)
{
    int i = blockIdx.x * blockDim.x + threadIdx.x;
    const int PR = Pp * Rr;
    const int BT = Bb * Tt;
    if (out_size >= PR + BT && i < BT)        out[PR + i]      = trig[i];
    if (out_size >= PR + BT + Pp && i < Pp)   out[PR + BT + i] = (float)labels[i];
}

// ---------------------------------------------------------------------------
extern "C" void kernel_launch(void* const* d_in, const int* in_sizes, int n_in,
                              void* d_out, int out_size)
{
    const float* x     = (const float*)d_in[0];
    const float* trig  = (const float*)d_in[1];
    const int*   bidx  = (const int*)  d_in[2];
    const int*   hidx  = (const int*)  d_in[3];
    const int*   hspan = (const int*)  d_in[4];
    const int*   tidx  = (const int*)  d_in[5];
    const int*   tspan = (const int*)  d_in[6];
    const int*   labels= (const int*)  d_in[7];
    const float* c1w   = (const float*)d_in[8];
    const float* c1b   = (const float*)d_in[9];
    const float* c2w   = (const float*)d_in[10];
    const float* c2b   = (const float*)d_in[11];
    const float* w1    = (const float*)d_in[12];
    const float* b1    = (const float*)d_in[13];
    const float* w2    = (const float*)d_in[14];
    const float* b2    = (const float*)d_in[15];
    const float* wr    = (const float*)d_in[16];
    const float* br    = (const float*)d_in[17];
    float* out = (float*)d_out;

    __nv_bfloat16 *pxh, *pxl, *px1h, *px1l, *pwt1h, *pwt1l, *pwt2h, *pwt2l;
    __nv_bfloat16 *pmxh, *pmxl, *pw1h, *pw1l, *pw2h, *pw2l, *ph1h, *ph1l;
    float *px1, *pxbte, *ph2;
    cudaGetSymbolAddress((void**)&pxh,   g_xh);
    cudaGetSymbolAddress((void**)&pxl,   g_xl);
    cudaGetSymbolAddress((void**)&px1h,  g_x1h);
    cudaGetSymbolAddress((void**)&px1l,  g_x1l);
    cudaGetSymbolAddress((void**)&pwt1h, g_wt1h);
    cudaGetSymbolAddress((void**)&pwt1l, g_wt1l);
    cudaGetSymbolAddress((void**)&pwt2h, g_wt2h);
    cudaGetSymbolAddress((void**)&pwt2l, g_wt2l);
    cudaGetSymbolAddress((void**)&pmxh,  g_mx_h);
    cudaGetSymbolAddress((void**)&pmxl,  g_mx_l);
    cudaGetSymbolAddress((void**)&pw1h,  g_w1h);
    cudaGetSymbolAddress((void**)&pw1l,  g_w1l);
    cudaGetSymbolAddress((void**)&pw2h,  g_w2h);
    cudaGetSymbolAddress((void**)&pw2l,  g_w2l);
    cudaGetSymbolAddress((void**)&ph1h,  g_h1h);
    cudaGetSymbolAddress((void**)&ph1l,  g_h1l);
    cudaGetSymbolAddress((void**)&px1,   g_x1);
    cudaGetSymbolAddress((void**)&pxbte, g_xbte);
    cudaGetSymbolAddress((void**)&ph2,   g_h2);

    static int smem_set = 0;
    if (!smem_set) {
        cudaFuncSetAttribute(fc_mma_kernel<true>,
                             cudaFuncAttributeMaxDynamicSharedMemorySize, FC_SMEM);
        cudaFuncSetAttribute(fc_mma_kernel<false>,
                             cudaFuncAttributeMaxDynamicSharedMemorySize, FC_SMEM);
        cudaFuncSetAttribute(conv_mma_kernel<0>,
                             cudaFuncAttributeMaxDynamicSharedMemorySize, CONV_SMEM);
        cudaFuncSetAttribute(conv_mma_kernel<1>,
                             cudaFuncAttributeMaxDynamicSharedMemorySize, CONV_SMEM);
        smem_set = 1;
    }

    // Conversions
    {
        dim3 tg(Tt / 32, Ee / 32, Bb);
        cvt_transpose_kernel<<<tg, 256>>>(x, pxh, pxl);   // x -> hi/lo (B,T,E)
    }
    cvt_wt_kernel<<<(Ee*Ee*3 + 255)/256, 256>>>(c1w, pwt1h, pwt1l);
    cvt_wt_kernel<<<(Ee*Ee*3 + 255)/256, 256>>>(c2w, pwt2h, pwt2l);
    cvt_hilo_kernel<<<(Hh*Ee + 255)/256, 256>>>(w1, pw1h, pw1l, Hh*Ee);
    cvt_hilo_kernel<<<(Hh*Hh + 255)/256, 256>>>(w2, pw2h, pw2l, Hh*Hh);

    // Conv blocks (tensor cores, fully async loads)
    {
        dim3 grid((Bb * Tt) / 128, Ee / 128);
        conv_mma_kernel<0><<<grid, 256, CONV_SMEM>>>(
            pxh, pxl, pwt1h, pwt1l, c1b, x, px1, px1h, px1l);
        conv_mma_kernel<1><<<grid, 256, CONV_SMEM>>>(
            px1h, px1l, pwt2h, pwt2l, c2b, px1, pxbte, nullptr, nullptr);
    }

    // Span max -> bf16 hi/lo
    span_kernel<<<Pp, 128>>>(bidx, hidx, hspan, tidx, tspan);

    // FC1 (mma bf16x3): (P,512)x(1024,512)^T -> h1 hi/lo, relu
    {
        dim3 grid(Hh / 128, Pp / 128);
        fc_mma_kernel<true><<<grid, 256, FC_SMEM>>>(
            pmxh, pmxl, pw1h, pw1l, b1, Ee, Hh, nullptr, ph1h, ph1l);
    }
    // FC2 (mma bf16x3): (P,1024)x(1024,1024)^T -> h2 fp32, relu
    {
        dim3 grid(Hh / 128, Pp / 128);
        fc_mma_kernel<false><<<grid, 256, FC_SMEM>>>(
            ph1h, ph1l, pw2h, pw2l, b2, Hh, Hh, ph2, nullptr, nullptr);
    }
    // FC3: split-K + reduce into d_out
    {
        dim3 grid(KSPLIT, Pp / 128);
        fc3_splitk_kernel<<<grid, 256>>>(ph2, wr);
        fc3_reduce_kernel<<<(Pp * Rr + 255) / 256, 256>>>(br, out);
    }
    // trig_attn + rel_labels passthrough
    pack_kernel<<<(8192 + 255) / 256, 256>>>(trig, labels, out, out_size);
}

// round 16
// speedup vs baseline: 1.0324x; 1.0005x over previous
#include <cuda_runtime.h>
#include <cuda_bf16.h>
#include <math.h>
#include <stdint.h>

// Problem constants
#define Bb 16
#define Ee 512
#define Tt 512
#define Hh 1024
#define Rr 32
#define Pp 8192
#define Ww 3
#define KSPLIT 4

// bf16 m16n8k16 tensor-core MMA (baseline PTX, valid on sm_103)
#define MMA16816(C, A, B) \
    asm volatile("mma.sync.aligned.m16n8k16.row.col.f32.bf16.bf16.f32 " \
        "{%0,%1,%2,%3}, {%4,%5,%6,%7}, {%8,%9}, {%0,%1,%2,%3};" \
        : "+f"((C)[0]), "+f"((C)[1]), "+f"((C)[2]), "+f"((C)[3]) \
        : "r"((A)[0]), "r"((A)[1]), "r"((A)[2]), "r"((A)[3]), \
          "r"((B)[0]), "r"((B)[1]))

#define LDSM_X4(R0, R1, R2, R3, addr) \
    asm volatile("ldmatrix.sync.aligned.m8n8.x4.shared.b16 {%0,%1,%2,%3}, [%4];" \
        : "=r"(R0), "=r"(R1), "=r"(R2), "=r"(R3) : "r"(addr))

__device__ __forceinline__ uint32_t smem_u32(const void* p) {
    uint32_t a;
    asm("{ .reg .u64 t; cvta.to.shared.u64 t, %1; cvt.u32.u64 %0, t; }" : "=r"(a) : "l"(p));
    return a;
}

// Scratch (device globals: allocation-free per harness rules)
__device__ float g_x1[Bb*Ee*Tt];                 // conv1 out fp32 (B,E,T)
__device__ float g_xbte[Bb*Tt*Ee];               // conv2 out fp32 (B,T,E)
__device__ __nv_bfloat16 g_xh[Bb*Tt*Ee];         // input x hi/lo (B,T,E) !
__device__ __nv_bfloat16 g_xl[Bb*Tt*Ee];
__device__ __nv_bfloat16 g_x1h[Bb*Tt*Ee];        // conv1 out hi/lo (B,T,E) !
__device__ __nv_bfloat16 g_x1l[Bb*Tt*Ee];
__device__ __nv_bfloat16 g_wt1h[3*Ee*Ee];        // conv weights [dk][eo][ei]
__device__ __nv_bfloat16 g_wt1l[3*Ee*Ee];
__device__ __nv_bfloat16 g_wt2h[3*Ee*Ee];
__device__ __nv_bfloat16 g_wt2l[3*Ee*Ee];
__device__ __nv_bfloat16 g_mx_h[Pp*Ee];
__device__ __nv_bfloat16 g_mx_l[Pp*Ee];
__device__ __nv_bfloat16 g_w1h[Hh*Ee];
__device__ __nv_bfloat16 g_w1l[Hh*Ee];
__device__ __nv_bfloat16 g_w2h[Hh*Hh];
__device__ __nv_bfloat16 g_w2l[Hh*Hh];
__device__ __nv_bfloat16 g_h1h[Pp*Hh];
__device__ __nv_bfloat16 g_h1l[Pp*Hh];
__device__ float g_h2[Pp*Hh];
__device__ float g_fc3p[KSPLIT*Pp*Rr];

// fp32 -> bf16 hi/lo (elementwise, for FC weights)
__global__ void cvt_hilo_kernel(const float* __restrict__ in,
                                __nv_bfloat16* __restrict__ hi,
                                __nv_bfloat16* __restrict__ lo, int n)
{
    int i = blockIdx.x * blockDim.x + threadIdx.x;
    if (i < n) {
        float x = in[i];
        __nv_bfloat16 h = __float2bfloat16(x);
        hi[i] = h;
        lo[i] = __float2bfloat16(x - __bfloat162float(h));
    }
}

// fp32 (B,E,T) -> bf16 hi/lo (B,T,E), 32x32 smem transpose
__global__ __launch_bounds__(256) void cvt_transpose_kernel(
    const float* __restrict__ in,
    __nv_bfloat16* __restrict__ hi,
    __nv_bfloat16* __restrict__ lo)
{
    __shared__ float tile[32][33];
    const int b  = blockIdx.z;
    const int e0 = blockIdx.y * 32;
    const int t0 = blockIdx.x * 32;
    const int tx = threadIdx.x & 31;
    const int ty = threadIdx.x >> 5;    // 0..7

    #pragma unroll
    for (int r = ty; r < 32; r += 8)
        tile[r][tx] = in[((size_t)b * Ee + e0 + r) * Tt + t0 + tx];
    __syncthreads();
    #pragma unroll
    for (int r = ty; r < 32; r += 8) {
        float v = tile[tx][r];          // (e_local=tx, t_local=r)
        __nv_bfloat16 h = __float2bfloat16(v);
        size_t o = ((size_t)b * Tt + t0 + r) * Ee + e0 + tx;
        hi[o] = h;
        lo[o] = __float2bfloat16(v - __bfloat162float(h));
    }
}

// conv weights (eo,ei,dk) -> transposed [dk][eo][ei] hi/lo
__global__ void cvt_wt_kernel(const float* __restrict__ w,
                              __nv_bfloat16* __restrict__ th,
                              __nv_bfloat16* __restrict__ tl)
{
    int i = blockIdx.x * blockDim.x + threadIdx.x;
    if (i < Ee * Ee * 3) {
        int eo  = i / (Ee * 3);
        int rem = i - eo * (Ee * 3);
        int ei  = rem / 3;
        int dk  = rem - ei * 3;
        float x = w[i];
        __nv_bfloat16 h = __float2bfloat16(x);
        int o = dk * (Ee * Ee) + eo * Ee + ei;
        th[o] = h;
        tl[o] = __float2bfloat16(x - __bfloat162float(h));
    }
}

// ---------------------------------------------------------------------------
// Conv residual block via mma.sync bf16x3 + ldmatrix; B via cp.async from
// (B,T,E)-layout hi/lo (fully async loads). Double-buffered.
// MODE 0: write g_x1 fp32 (B,E,T) + g_x1h/l bf16 (B,T,E)
// MODE 1: write g_xbte fp32 (B,T,E)
// ---------------------------------------------------------------------------
#define CROWB 80
#define CAH 0
#define CAL (384*CROWB)
#define CBH (2*384*CROWB)
#define CBL (CBH + 130*CROWB)
#define CBUF (CBL + 130*CROWB)
#define CONV_SMEM (2*CBUF)

template<int MODE>
__global__ __launch_bounds__(256, 1) void conv_mma_kernel(
    const __nv_bfloat16* __restrict__ xh_g, const __nv_bfloat16* __restrict__ xl_g,
    const __nv_bfloat16* __restrict__ wth,  const __nv_bfloat16* __restrict__ wtl,
    const float* __restrict__ bias, const float* __restrict__ resid,
    float* __restrict__ outf,
    __nv_bfloat16* __restrict__ outh, __nv_bfloat16* __restrict__ outl)
{
    extern __shared__ __align__(16) unsigned char SM[];

    const int tid  = threadIdx.x;
    const int wid  = tid >> 5;
    const int lane = tid & 31;
    const int g    = lane >> 2;
    const int tq   = lane & 3;
    const int n0   = blockIdx.x * 128;
    const int m0   = blockIdx.y * 128;
    const int b    = n0 >> 9;
    const int t0   = n0 & 511;
    const int wm   = wid & 1;
    const int wn   = wid >> 1;
    const uint32_t smbase = smem_u32(SM);

    const int lrow = lane & 15;
    const int lkh  = lane >> 4;
    const int brow = lane & 7;
    const int bkh  = (lane >> 3) & 1;
    const int bts  = lane >> 4;

    // (B,T,E) layout
    const __nv_bfloat16* __restrict__ xh_b = xh_g + (size_t)b * Tt * Ee;
    const __nv_bfloat16* __restrict__ xl_b = xl_g + (size_t)b * Tt * Ee;

    float acc[4][4][4];
    #pragma unroll
    for (int i = 0; i < 4; i++)
        #pragma unroll
        for (int j = 0; j < 4; j++)
            #pragma unroll
            for (int q = 0; q < 4; q++) acc[i][j][q] = 0.f;

    // ---- chunk loader: all cp.async ----
    auto issue = [&](int kbeg, int bsel) {
        uint32_t base = smbase + bsel * CBUF;
        unsigned char* bb = SM + bsel * CBUF;
        // A: weights, 3 taps x 128 eo x 32 ei, hi+lo = 3072 x 16B, 12/thread
        #pragma unroll
        for (int i = 0; i < 12; i++) {
            int idx = tid + 256 * i;
            int hl  = (idx >= 1536);
            int r   = hl ? (idx - 1536) : idx;
            int row = r >> 2;
            int q   = r & 3;
            int dk  = row >> 7;
            int eo  = row & 127;
            const __nv_bfloat16* gsrc =
                (hl ? wtl : wth) + (size_t)dk * (Ee * Ee) + (size_t)(m0 + eo) * Ee + kbeg + q * 8;
            uint32_t daddr = base + (hl ? CAL : CAH) + row * CROWB + q * 16;
            asm volatile("cp.async.cg.shared.global [%0], [%1], 16;"
                         :: "r"(daddr), "l"(gsrc));
        }
        // B: x (B,T,E): 130 rows (t0-1..t0+128) x 32 ei (64B = 4x16B), hi+lo
        // 1040 units, 5 iters with guard
        #pragma unroll
        for (int i = 0; i < 5; i++) {
            int idx = tid + 256 * i;
            if (idx < 1040) {
                int hl  = (idx >= 520);
                int r   = hl ? (idx - 520) : idx;
                int row = r >> 2;          // 0..129, global t = t0-1+row
                int u   = r & 3;
                int t   = t0 - 1 + row;
                uint32_t off = (hl ? CBL : CBH) + row * CROWB + u * 16;
                if ((unsigned)t < (unsigned)Tt) {
                    const __nv_bfloat16* gsrc =
                        (hl ? xl_b : xh_b) + (size_t)t * Ee + kbeg + u * 8;
                    asm volatile("cp.async.cg.shared.global [%0], [%1], 16;"
                                 :: "r"(base + off), "l"(gsrc));
                } else {
                    *(uint4*)(bb + off) = make_uint4(0, 0, 0, 0);
                }
            }
        }
        asm volatile("cp.async.commit_group;" ::: "memory");
    };

    // ---- compute one K=32 chunk (ldmatrix) ----
    auto compute = [&](int bsel) {
        const uint32_t base = smbase + bsel * CBUF;
        #pragma unroll
        for (int ko = 0; ko < 32; ko += 16) {
            #pragma unroll
            for (int dk = 0; dk < 3; dk++) {
                uint32_t ah[4][4], al[4][4], bh[4][2], bl[4][2];
                #pragma unroll
                for (int mt = 0; mt < 4; mt++) {
                    int row = dk * 128 + wm * 64 + mt * 16 + lrow;
                    uint32_t aoff = row * CROWB + (ko + 8 * lkh) * 2;
                    LDSM_X4(ah[mt][0], ah[mt][1], ah[mt][2], ah[mt][3], base + CAH + aoff);
                    LDSM_X4(al[mt][0], al[mt][1], al[mt][2], al[mt][3], base + CAL + aoff);
                }
                #pragma unroll
                for (int p = 0; p < 2; p++) {
                    int row = wn * 32 + p * 16 + bts * 8 + brow + dk;
                    uint32_t boff = row * CROWB + (ko + 8 * bkh) * 2;
                    LDSM_X4(bh[2*p][0], bh[2*p][1], bh[2*p+1][0], bh[2*p+1][1], base + CBH + boff);
                    LDSM_X4(bl[2*p][0], bl[2*p][1], bl[2*p+1][0], bl[2*p+1][1], base + CBL + boff);
                }
                #pragma unroll
                for (int mt = 0; mt < 4; mt++)
                    #pragma unroll
                    for (int nt = 0; nt < 4; nt++)
                        MMA16816(acc[mt][nt], ah[mt], bh[nt]);
                #pragma unroll
                for (int mt = 0; mt < 4; mt++)
                    #pragma unroll
                    for (int nt = 0; nt < 4; nt++)
                        MMA16816(acc[mt][nt], ah[mt], bl[nt]);
                #pragma unroll
                for (int mt = 0; mt < 4; mt++)
                    #pragma unroll
                    for (int nt = 0; nt < 4; nt++)
                        MMA16816(acc[mt][nt], al[mt], bh[nt]);
            }
        }
    };

    const int NC = Ee / 32;
    issue(0, 0);
    for (int c = 0; c < NC; c++) {
        if (c + 1 < NC) {
            issue((c + 1) * 32, (c + 1) & 1);
            asm volatile("cp.async.wait_group 1;" ::: "memory");
        } else {
            asm volatile("cp.async.wait_group 0;" ::: "memory");
        }
        __syncthreads();
        compute(c & 1);
        __syncthreads();
    }

    // ---- epilogue ----
    #pragma unroll
    for (int mt = 0; mt < 4; mt++) {
        const int eo0 = m0 + wm * 64 + mt * 16 + g;
        const int eo1 = eo0 + 8;
        const float b0v = bias[eo0], b1v = bias[eo1];
        #pragma unroll
        for (int nt = 0; nt < 4; nt++) {
            const int n = t0 + wn * 32 + nt * 8 + tq * 2;
            float v00 = acc[mt][nt][0] + b0v;
            float v01 = acc[mt][nt][1] + b0v;
            float v10 = acc[mt][nt][2] + b1v;
            float v11 = acc[mt][nt][3] + b1v;
            v00 = (v00 > 0.f) ? v00 : 0.f;
            v01 = (v01 > 0.f) ? v01 : 0.f;
            v10 = (v10 > 0.f) ? v10 : 0.f;
            v11 = (v11 > 0.f) ? v11 : 0.f;
            size_t i00 = ((size_t)b * Ee + eo0) * Tt + n;
            size_t i10 = ((size_t)b * Ee + eo1) * Tt + n;
            v00 += resid[i00];     v01 += resid[i00 + 1];
            v10 += resid[i10];     v11 += resid[i10 + 1];
            if (MODE == 0) {
                outf[i00] = v00; outf[i00 + 1] = v01;
                outf[i10] = v10; outf[i10 + 1] = v11;
                // hi/lo to (B,T,E) for conv2's async B loads
                size_t j00 = ((size_t)b * Tt + n) * Ee + eo0;  // (t=n, eo0)
                __nv_bfloat16 h00 = __float2bfloat16(v00);
                __nv_bfloat16 h01 = __float2bfloat16(v01);
                __nv_bfloat16 h10 = __float2bfloat16(v10);
                __nv_bfloat16 h11 = __float2bfloat16(v11);
                outh[j00]          = h00;
                outh[j00 + Ee]     = h01;
                outh[j00 + 8]      = h10;
                outh[j00 + Ee + 8] = h11;
                outl[j00]          = __float2bfloat16(v00 - __bfloat162float(h00));
                outl[j00 + Ee]     = __float2bfloat16(v01 - __bfloat162float(h01));
                outl[j00 + 8]      = __float2bfloat16(v10 - __bfloat162float(h10));
                outl[j00 + Ee + 8] = __float2bfloat16(v11 - __bfloat162float(h11));
            } else {
                outf[((size_t)b * Tt + n)     * Ee + eo0] = v00;
                outf[((size_t)b * Tt + n + 1) * Ee + eo0] = v01;
                outf[((size_t)b * Tt + n)     * Ee + eo1] = v10;
                outf[((size_t)b * Tt + n + 1) * Ee + eo1] = v11;
            }
        }
    }
}

// ---------------------------------------------------------------------------
// Span max gather -> bf16 hi/lo
// ---------------------------------------------------------------------------
__global__ __launch_bounds__(128) void span_kernel(
    const int* __restrict__ bidx,
    const int* __restrict__ hidx, const int* __restrict__ hspan,
    const int* __restrict__ tidx, const int* __restrict__ tspan)
{
    const int p  = blockIdx.x;
    const int e4 = threadIdx.x;
    const int b  = bidx[p];
    const float4* __restrict__ base = (const float4*)g_xbte + (size_t)b * Tt * (Ee / 4);

    const int h0 = hidx[p], hs = hspan[p];
    const int t0 = tidx[p], ts = tspan[p];

    float4 hm = make_float4(-INFINITY, -INFINITY, -INFINITY, -INFINITY);
    for (int s = 0; s < hs; s++) {
        float4 v = base[(size_t)(h0 + s) * (Ee / 4) + e4];
        hm.x = fmaxf(hm.x, v.x); hm.y = fmaxf(hm.y, v.y);
        hm.z = fmaxf(hm.z, v.z); hm.w = fmaxf(hm.w, v.w);
    }
    float4 tm = make_float4(-INFINITY, -INFINITY, -INFINITY, -INFINITY);
    for (int s = 0; s < ts; s++) {
        float4 v = base[(size_t)(t0 + s) * (Ee / 4) + e4];
        tm.x = fmaxf(tm.x, v.x); tm.y = fmaxf(tm.y, v.y);
        tm.z = fmaxf(tm.z, v.z); tm.w = fmaxf(tm.w, v.w);
    }
    float o[4] = {hm.x + tm.x, hm.y + tm.y, hm.z + tm.z, hm.w + tm.w};

    size_t off = (size_t)p * Ee + e4 * 4;
    #pragma unroll
    for (int j = 0; j < 4; j++) {
        __nv_bfloat16 h = __float2bfloat16(o[j]);
        __nv_bfloat16 l = __float2bfloat16(o[j] - __bfloat162float(h));
        g_mx_h[off + j] = h;
        g_mx_l[off + j] = l;
    }
}

// ---------------------------------------------------------------------------
// Tensor-core bf16x3 NT GEMM (FC1/FC2): ldmatrix + 3-stage cp.async ring,
// single __syncthreads per chunk.
// ---------------------------------------------------------------------------
#define SROW 40
#define SEC_ELEMS (128*SROW)
#define SEC_BYTES (SEC_ELEMS*2)
#define BUF_BYTES (4*SEC_BYTES)
#define FC_SMEM   (3*BUF_BYTES)

template<bool HILO>
__global__ __launch_bounds__(256, 1) void fc_mma_kernel(
    const __nv_bfloat16* __restrict__ Ah, const __nv_bfloat16* __restrict__ Al,
    const __nv_bfloat16* __restrict__ Bh, const __nv_bfloat16* __restrict__ Bl,
    const float* __restrict__ bias, int K, int N,
    float* __restrict__ Cf,
    __nv_bfloat16* __restrict__ Ch, __nv_bfloat16* __restrict__ Cl)
{
    extern __shared__ __align__(16) unsigned char SM[];

    const int tid  = threadIdx.x;
    const int wid  = tid >> 5;
    const int lane = tid & 31;
    const int g    = lane >> 2;
    const int t    = lane & 3;
    const int n0   = blockIdx.x * 128;
    const int m0   = blockIdx.y * 128;
    const int wm   = wid & 1;
    const int wn   = wid >> 1;
    const uint32_t smbase = smem_u32(SM);

    const int lrow = lane & 15;
    const int lkh  = lane >> 4;
    const int brow = lane & 7;
    const int bkh  = (lane >> 3) & 1;
    const int bts  = lane >> 4;

    float acc[4][4][4];
    #pragma unroll
    for (int i = 0; i < 4; i++)
        #pragma unroll
        for (int j = 0; j < 4; j++)
            #pragma unroll
            for (int q = 0; q < 4; q++) acc[i][j][q] = 0.f;

    auto issue_chunk = [&](int kbeg, int bsel) {
        uint32_t base = smbase + bsel * BUF_BYTES;
        #pragma unroll
        for (int i = 0; i < 8; i++) {
            int idx = tid + 256 * i;
            int sec = idx >> 9;
            int rem = idx & 511;
            int row = rem >> 2;
            int q   = rem & 3;
            const __nv_bfloat16* gsrc;
            if (sec == 0)      gsrc = Ah + (size_t)(m0 + row) * K + kbeg + q * 8;
            else if (sec == 1) gsrc = Al + (size_t)(m0 + row) * K + kbeg + q * 8;
            else if (sec == 2) gsrc = Bh + (size_t)(n0 + row) * K + kbeg + q * 8;
            else               gsrc = Bl + (size_t)(n0 + row) * K + kbeg + q * 8;
            uint32_t daddr = base + sec * SEC_BYTES + row * (SROW * 2) + q * 16;
            asm volatile("cp.async.cg.shared.global [%0], [%1], 16;"
                         :: "r"(daddr), "l"(gsrc));
        }
        asm volatile("cp.async.commit_group;" ::: "memory");
    };

    auto compute_chunk = [&](int bsel) {
        const uint32_t base = smbase + bsel * BUF_BYTES;
        #pragma unroll
        for (int ko = 0; ko < 32; ko += 16) {
            uint32_t ah[4][4], al[4][4], bh[4][2], bl[4][2];
            #pragma unroll
            for (int mt = 0; mt < 4; mt++) {
                uint32_t aoff = (wm * 64 + mt * 16 + lrow) * (SROW * 2) + (ko + 8 * lkh) * 2;
                LDSM_X4(ah[mt][0], ah[mt][1], ah[mt][2], ah[mt][3], base + aoff);
                LDSM_X4(al[mt][0], al[mt][1], al[mt][2], al[mt][3], base + SEC_BYTES + aoff);
            }
            #pragma unroll
            for (int p = 0; p < 2; p++) {
                uint32_t boff = (wn * 32 + p * 16 + bts * 8 + brow) * (SROW * 2) + (ko + 8 * bkh) * 2;
                LDSM_X4(bh[2*p][0], bh[2*p][1], bh[2*p+1][0], bh[2*p+1][1],
                        base + 2 * SEC_BYTES + boff);
                LDSM_X4(bl[2*p][0], bl[2*p][1], bl[2*p+1][0], bl[2*p+1][1],
                        base + 3 * SEC_BYTES + boff);
            }
            #pragma unroll
            for (int mt = 0; mt < 4; mt++)
                #pragma unroll
                for (int nt = 0; nt < 4; nt++)
                    MMA16816(acc[mt][nt], ah[mt], bh[nt]);
            #pragma unroll
            for (int mt = 0; mt < 4; mt++)
                #pragma unroll
                for (int nt = 0; nt < 4; nt++)
                    MMA16816(acc[mt][nt], ah[mt], bl[nt]);
            #pragma unroll
            for (int mt = 0; mt < 4; mt++)
                #pragma unroll
                for (int nt = 0; nt < 4; nt++)
                    MMA16816(acc[mt][nt], al[mt], bh[nt]);
        }
    };

    const int NC = K / 32;
    // 3-stage ring: 2 chunks in flight, one barrier per chunk
    issue_chunk(0, 0);
    issue_chunk(32, 1);
    int bsel = 0;
    for (int c = 0; c < NC; c++) {
        if (c == NC - 1) {
            asm volatile("cp.async.wait_group 0;" ::: "memory");
        } else {
            asm volatile("cp.async.wait_group 1;" ::: "memory");
        }
        __syncthreads();
        if (c + 2 < NC) {
            int nb = bsel + 2; if (nb >= 3) nb -= 3;
            issue_chunk((c + 2) * 32, nb);
        }
        compute_chunk(bsel);
        if (++bsel == 3) bsel = 0;
    }

    #pragma unroll
    for (int mt = 0; mt < 4; mt++) {
        const int m = m0 + wm * 64 + mt * 16 + g;
        #pragma unroll
        for (int nt = 0; nt < 4; nt++) {
            const int n = n0 + wn * 32 + nt * 8 + t * 2;
            float b0 = bias[n], b1 = bias[n + 1];
            float v00 = acc[mt][nt][0] + b0;
            float v01 = acc[mt][nt][1] + b1;
            float v10 = acc[mt][nt][2] + b0;
            float v11 = acc[mt][nt][3] + b1;
            v00 = (v00 > 0.f) ? v00 : 0.f;
            v01 = (v01 > 0.f) ? v01 : 0.f;
            v10 = (v10 > 0.f) ? v10 : 0.f;
            v11 = (v11 > 0.f) ? v11 : 0.f;
            if (HILO) {
                __nv_bfloat16 h00 = __float2bfloat16(v00);
                __nv_bfloat16 h01 = __float2bfloat16(v01);
                __nv_bfloat16 h10 = __float2bfloat16(v10);
                __nv_bfloat16 h11 = __float2bfloat16(v11);
                __nv_bfloat162 hp0; hp0.x = h00; hp0.y = h01;
                __nv_bfloat162 hp1; hp1.x = h10; hp1.y = h11;
                __nv_bfloat162 lp0;
                lp0.x = __float2bfloat16(v00 - __bfloat162float(h00));
                lp0.y = __float2bfloat16(v01 - __bfloat162float(h01));
                __nv_bfloat162 lp1;
                lp1.x = __float2bfloat16(v10 - __bfloat162float(h10));
                lp1.y = __float2bfloat16(v11 - __bfloat162float(h11));
                *(__nv_bfloat162*)(Ch + (size_t)m * N + n)       = hp0;
                *(__nv_bfloat162*)(Cl + (size_t)m * N + n)       = lp0;
                *(__nv_bfloat162*)(Ch + (size_t)(m + 8) * N + n) = hp1;
                *(__nv_bfloat162*)(Cl + (size_t)(m + 8) * N + n) = lp1;
            } else {
                float2 f0 = make_float2(v00, v01);
                float2 f1 = make_float2(v10, v11);
                *(float2*)(Cf + (size_t)m * N + n)       = f0;
                *(float2*)(Cf + (size_t)(m + 8) * N + n) = f1;
            }
        }
    }
}

// ---------------------------------------------------------------------------
// FC3 split-K GEMM (scalar) + reduce — unchanged
// ---------------------------------------------------------------------------
__global__ __launch_bounds__(256, 2) void fc3_splitk_kernel(
    const float* __restrict__ A,
    const float* __restrict__ Wr)
{
    __shared__ float As[2][8][128];
    __shared__ float Bs[2][8][32];

    const int tid = threadIdx.x;
    const int ks  = blockIdx.x;
    const int m0  = blockIdx.y * 128;
    const int kbeg = ks * (Hh / KSPLIT);
    const int tx = tid & 7;
    const int ty = tid >> 3;

    float acc[4][4];
    #pragma unroll
    for (int i = 0; i < 4; i++)
        #pragma unroll
        for (int j = 0; j < 4; j++) acc[i][j] = 0.f;

    const int r = tid >> 1;
    const int s = (tid & 1) * 4;
    const float* __restrict__ Arow = A + (size_t)(m0 + r) * Hh + kbeg + s;
    const float* __restrict__ Brow = Wr + (size_t)(tid >> 1) * Hh + kbeg + ((tid & 1) * 4);

    float4 a_n; float4 b_n = make_float4(0.f,0.f,0.f,0.f);

    a_n = *(const float4*)&Arow[0];
    if (tid < 64) b_n = *(const float4*)&Brow[0];
    As[0][s + 0][r] = a_n.x; As[0][s + 1][r] = a_n.y;
    As[0][s + 2][r] = a_n.z; As[0][s + 3][r] = a_n.w;
    if (tid < 64) {
        int bn = tid >> 1, bs = (tid & 1) * 4;
        Bs[0][bs + 0][bn] = b_n.x; Bs[0][bs + 1][bn] = b_n.y;
        Bs[0][bs + 2][bn] = b_n.z; Bs[0][bs + 3][bn] = b_n.w;
    }
    __syncthreads();

    int buf = 0;
    const int KC = Hh / KSPLIT;
    for (int k0 = 8; k0 <= KC; k0 += 8) {
        const bool more = (k0 < KC);
        if (more) {
            a_n = *(const float4*)&Arow[k0];
            if (tid < 64) b_n = *(const float4*)&Brow[k0];
        }

        #pragma unroll
        for (int k = 0; k < 8; k++) {
            float4 a0 = *(const float4*)&As[buf][k][ty * 4];
            float4 b0 = *(const float4*)&Bs[buf][k][tx * 4];
            float av[4] = {a0.x, a0.y, a0.z, a0.w};
            float bv[4] = {b0.x, b0.y, b0.z, b0.w};
            #pragma unroll
            for (int ii = 0; ii < 4; ii++)
                #pragma unroll
                for (int jj = 0; jj < 4; jj++)
                    acc[ii][jj] += av[ii] * bv[jj];
        }

        if (more) {
            int nb = buf ^ 1;
            As[nb][s + 0][r] = a_n.x; As[nb][s + 1][r] = a_n.y;
            As[nb][s + 2][r] = a_n.z; As[nb][s + 3][r] = a_n.w;
            if (tid < 64) {
                int bn = tid >> 1, bs = (tid & 1) * 4;
                Bs[nb][bs + 0][bn] = b_n.x; Bs[nb][bs + 1][bn] = b_n.y;
                Bs[nb][bs + 2][bn] = b_n.z; Bs[nb][bs + 3][bn] = b_n.w;
            }
            buf = nb;
            __syncthreads();
        }
    }

    float* __restrict__ part = (float*)g_fc3p + (size_t)ks * Pp * Rr;
    #pragma unroll
    for (int ii = 0; ii < 4; ii++) {
        int m = m0 + ty * 4 + ii;
        #pragma unroll
        for (int jj = 0; jj < 4; jj++) {
            int nn = tx * 4 + jj;
            part[(size_t)m * Rr + nn] = acc[ii][jj];
        }
    }
}

__global__ void fc3_reduce_kernel(const float* __restrict__ br,
                                  float* __restrict__ out)
{
    int i = blockIdx.x * blockDim.x + threadIdx.x;
    if (i < Pp * Rr) {
        const float* p = (const float*)g_fc3p;
        float v = p[i] + p[i + Pp*Rr] + p[i + 2*Pp*Rr] + p[i + 3*Pp*Rr];
        out[i] = v + br[i & (Rr - 1)];
    }
}

// ---------------------------------------------------------------------------
__global__ void pack_kernel(const float* __restrict__ trig,
                            const int* __restrict__ labels,
                            float* __restrict__ out, int out_size)
{
    int i = blockIdx.x * blockDim.x + threadIdx.x;
    const int PR = Pp * Rr;
    const int BT = Bb * Tt;
    if (out_size >= PR + BT && i < BT)        out[PR + i]      = trig[i];
    if (out_size >= PR + BT + Pp && i < Pp)   out[PR + BT + i] = (float)labels[i];
}

// ---------------------------------------------------------------------------
extern "C" void kernel_launch(void* const* d_in, const int* in_sizes, int n_in,
                              void* d_out, int out_size)
{
    const float* x     = (const float*)d_in[0];
    const float* trig  = (const float*)d_in[1];
    const int*   bidx  = (const int*)  d_in[2];
    const int*   hidx  = (const int*)  d_in[3];
    const int*   hspan = (const int*)  d_in[4];
    const int*   tidx  = (const int*)  d_in[5];
    const int*   tspan = (const int*)  d_in[6];
    const int*   labels= (const int*)  d_in[7];
    const float* c1w   = (const float*)d_in[8];
    const float* c1b   = (const float*)d_in[9];
    const float* c2w   = (const float*)d_in[10];
    const float* c2b   = (const float*)d_in[11];
    const float* w1    = (const float*)d_in[12];
    const float* b1    = (const float*)d_in[13];
    const float* w2    = (const float*)d_in[14];
    const float* b2    = (const float*)d_in[15];
    const float* wr    = (const float*)d_in[16];
    const float* br    = (const float*)d_in[17];
    float* out = (float*)d_out;

    __nv_bfloat16 *pxh, *pxl, *px1h, *px1l, *pwt1h, *pwt1l, *pwt2h, *pwt2l;
    __nv_bfloat16 *pmxh, *pmxl, *pw1h, *pw1l, *pw2h, *pw2l, *ph1h, *ph1l;
    float *px1, *pxbte, *ph2;
    cudaGetSymbolAddress((void**)&pxh,   g_xh);
    cudaGetSymbolAddress((void**)&pxl,   g_xl);
    cudaGetSymbolAddress((void**)&px1h,  g_x1h);
    cudaGetSymbolAddress((void**)&px1l,  g_x1l);
    cudaGetSymbolAddress((void**)&pwt1h, g_wt1h);
    cudaGetSymbolAddress((void**)&pwt1l, g_wt1l);
    cudaGetSymbolAddress((void**)&pwt2h, g_wt2h);
    cudaGetSymbolAddress((void**)&pwt2l, g_wt2l);
    cudaGetSymbolAddress((void**)&pmxh,  g_mx_h);
    cudaGetSymbolAddress((void**)&pmxl,  g_mx_l);
    cudaGetSymbolAddress((void**)&pw1h,  g_w1h);
    cudaGetSymbolAddress((void**)&pw1l,  g_w1l);
    cudaGetSymbolAddress((void**)&pw2h,  g_w2h);
    cudaGetSymbolAddress((void**)&pw2l,  g_w2l);
    cudaGetSymbolAddress((void**)&ph1h,  g_h1h);
    cudaGetSymbolAddress((void**)&ph1l,  g_h1l);
    cudaGetSymbolAddress((void**)&px1,   g_x1);
    cudaGetSymbolAddress((void**)&pxbte, g_xbte);
    cudaGetSymbolAddress((void**)&ph2,   g_h2);

    static int smem_set = 0;
    if (!smem_set) {
        cudaFuncSetAttribute(fc_mma_kernel<true>,
                             cudaFuncAttributeMaxDynamicSharedMemorySize, FC_SMEM);
        cudaFuncSetAttribute(fc_mma_kernel<false>,
                             cudaFuncAttributeMaxDynamicSharedMemorySize, FC_SMEM);
        cudaFuncSetAttribute(conv_mma_kernel<0>,
                             cudaFuncAttributeMaxDynamicSharedMemorySize, CONV_SMEM);
        cudaFuncSetAttribute(conv_mma_kernel<1>,
                             cudaFuncAttributeMaxDynamicSharedMemorySize, CONV_SMEM);
        smem_set = 1;
    }

    // Conversions
    {
        dim3 tg(Tt / 32, Ee / 32, Bb);
        cvt_transpose_kernel<<<tg, 256>>>(x, pxh, pxl);   // x -> hi/lo (B,T,E)
    }
    cvt_wt_kernel<<<(Ee*Ee*3 + 255)/256, 256>>>(c1w, pwt1h, pwt1l);
    cvt_wt_kernel<<<(Ee*Ee*3 + 255)/256, 256>>>(c2w, pwt2h, pwt2l);
    cvt_hilo_kernel<<<(Hh*Ee + 255)/256, 256>>>(w1, pw1h, pw1l, Hh*Ee);
    cvt_hilo_kernel<<<(Hh*Hh + 255)/256, 256>>>(w2, pw2h, pw2l, Hh*Hh);

    // Conv blocks (tensor cores, fully async loads)
    {
        dim3 grid((Bb * Tt) / 128, Ee / 128);
        conv_mma_kernel<0><<<grid, 256, CONV_SMEM>>>(
            pxh, pxl, pwt1h, pwt1l, c1b, x, px1, px1h, px1l);
        conv_mma_kernel<1><<<grid, 256, CONV_SMEM>>>(
            px1h, px1l, pwt2h, pwt2l, c2b, px1, pxbte, nullptr, nullptr);
    }

    // Span max -> bf16 hi/lo
    span_kernel<<<Pp, 128>>>(bidx, hidx, hspan, tidx, tspan);

    // FC1 (mma bf16x3): (P,512)x(1024,512)^T -> h1 hi/lo, relu
    {
        dim3 grid(Hh / 128, Pp / 128);
        fc_mma_kernel<true><<<grid, 256, FC_SMEM>>>(
            pmxh, pmxl, pw1h, pw1l, b1, Ee, Hh, nullptr, ph1h, ph1l);
    }
    // FC2 (mma bf16x3): (P,1024)x(1024,1024)^T -> h2 fp32, relu
    {
        dim3 grid(Hh / 128, Pp / 128);
        fc_mma_kernel<false><<<grid, 256, FC_SMEM>>>(
            ph1h, ph1l, pw2h, pw2l, b2, Hh, Hh, ph2, nullptr, nullptr);
    }
    // FC3: split-K + reduce into d_out
    {
        dim3 grid(KSPLIT, Pp / 128);
        fc3_splitk_kernel<<<grid, 256>>>(ph2, wr);
        fc3_reduce_kernel<<<(Pp * Rr + 255) / 256, 256>>>(br, out);
    }
    // trig_attn + rel_labels passthrough
    pack_kernel<<<(8192 + 255) / 256, 256>>>(trig, labels, out, out_size);
}